// round 1
// baseline (speedup 1.0000x reference)
#include <cuda_runtime.h>
#include <math.h>

#define SEQ 2048
#define HID 3584
#define NH 28
#define NKV 4
#define GRP 7
#define HD 128
#define SOFT_SCALE 0.08838834764831845f   // 1/sqrt(128)

// ---------------- scratch (static device globals; no runtime allocation) ----
__device__ float g_q[SEQ * NH * HD];    // [s][head][d]  28 MB
__device__ float g_k[SEQ * NKV * HD];   // [s][kvh][d]    4 MB
__device__ float g_v[SEQ * NKV * HD];   //                4 MB
__device__ float g_o[SEQ * NH * HD];    // attention out 28 MB

// ---------------- SGEMM: C[M,N] = A[M,K] * B[N,K]^T + bias ------------------
// 128x128 block tile, BK=8, 256 threads, 8x8 per-thread microtile.
__global__ __launch_bounds__(256) void sgemm_bias(
    const float* __restrict__ A, const float* __restrict__ B,
    const float* __restrict__ bias, float* __restrict__ C,
    int M, int N, int K)
{
    __shared__ float As[8][128];
    __shared__ float Bs[8][128];

    const int tid = threadIdx.x;
    const int tx = tid & 15;        // 16 col groups
    const int ty = tid >> 4;        // 16 row groups
    const int bx = blockIdx.x;      // N tile
    const int by = blockIdx.y;      // M tile

    const int lrow = tid >> 1;            // 0..127
    const int lcol = (tid & 1) * 4;       // 0 or 4

    const float* Ap = A + (size_t)(by * 128 + lrow) * K + lcol;
    const float* Bp = B + (size_t)(bx * 128 + lrow) * K + lcol;

    float acc[8][8];
#pragma unroll
    for (int i = 0; i < 8; i++)
#pragma unroll
        for (int j = 0; j < 8; j++) acc[i][j] = 0.f;

    for (int k0 = 0; k0 < K; k0 += 8) {
        float4 a = *(const float4*)(Ap + k0);
        float4 b = *(const float4*)(Bp + k0);
        As[lcol + 0][lrow] = a.x;
        As[lcol + 1][lrow] = a.y;
        As[lcol + 2][lrow] = a.z;
        As[lcol + 3][lrow] = a.w;
        Bs[lcol + 0][lrow] = b.x;
        Bs[lcol + 1][lrow] = b.y;
        Bs[lcol + 2][lrow] = b.z;
        Bs[lcol + 3][lrow] = b.w;
        __syncthreads();

#pragma unroll
        for (int kk = 0; kk < 8; kk++) {
            float ra[8], rb[8];
            *(float4*)(ra)     = *(const float4*)(&As[kk][ty * 8]);
            *(float4*)(ra + 4) = *(const float4*)(&As[kk][ty * 8 + 4]);
            *(float4*)(rb)     = *(const float4*)(&Bs[kk][tx * 8]);
            *(float4*)(rb + 4) = *(const float4*)(&Bs[kk][tx * 8 + 4]);
#pragma unroll
            for (int i = 0; i < 8; i++)
#pragma unroll
                for (int j = 0; j < 8; j++)
                    acc[i][j] = fmaf(ra[i], rb[j], acc[i][j]);
        }
        __syncthreads();
    }

#pragma unroll
    for (int i = 0; i < 8; i++) {
        int row = by * 128 + ty * 8 + i;
#pragma unroll
        for (int j = 0; j < 8; j++) {
            int col = bx * 128 + tx * 8 + j;
            float bb = bias ? bias[col] : 0.f;
            C[(size_t)row * N + col] = acc[i][j] + bb;
        }
    }
}

// ---------------- RoPE (in place on g_q, g_k) --------------------------------
__global__ void rope_kernel(const float* __restrict__ cosT,
                            const float* __restrict__ sinT)
{
    const int s = blockIdx.x;
    const int d = threadIdx.x;  // 0..127
    const float c  = cosT[s * HD + d];
    const float sn = sinT[s * HD + d];

    for (int h = 0; h < NH; h++) {
        float* row = g_q + ((size_t)s * NH + h) * HD;
        float x  = row[d];
        float xo = row[d ^ 64];
        float r  = (d < 64) ? -xo : xo;
        __syncthreads();               // all reads before any write
        row[d] = x * c + r * sn;
        __syncthreads();
    }
    for (int h = 0; h < NKV; h++) {
        float* row = g_k + ((size_t)s * NKV + h) * HD;
        float x  = row[d];
        float xo = row[d ^ 64];
        float r  = (d < 64) ? -xo : xo;
        __syncthreads();
        row[d] = x * c + r * sn;
        __syncthreads();
    }
}

// ---------------- Flash attention (fp32, online softmax) ---------------------
// grid (SEQ/64, NH); 256 threads; BQ=BKV=64.
// smem: Qs[64][129] Ks[64][129] Vs[64][132] Ps[64][65] + kdoc[64]
#define QS_STRIDE 129
#define VS_STRIDE 132
#define PS_STRIDE 65
#define FLASH_SMEM ((64*129 + 64*129 + 64*132 + 64*65) * 4 + 64 * 4)

__global__ __launch_bounds__(256) void flash_kernel(const int* __restrict__ doc)
{
    extern __shared__ float sm[];
    float* Qs = sm;                       // [64][129]
    float* Ks = Qs + 64 * QS_STRIDE;      // [64][129]
    float* Vs = Ks + 64 * QS_STRIDE;      // [64][132]
    float* Ps = Vs + 64 * VS_STRIDE;      // [64][65]
    int* kdoc = (int*)(Ps + 64 * PS_STRIDE);

    const int qb   = blockIdx.x;
    const int head = blockIdx.y;
    const int kvh  = head / GRP;
    const int q0   = qb * 64;
    const int tid  = threadIdx.x;
    const int tx   = tid & 15;   // key cols (score) / dim cols (O)
    const int ty   = tid >> 4;   // q rows

    // load Q tile
    for (int idx = tid; idx < 64 * 128; idx += 256) {
        int r = idx >> 7, d = idx & 127;
        Qs[r * QS_STRIDE + d] = g_q[((size_t)(q0 + r) * NH + head) * HD + d];
    }

    int   qdoc[4];
    float m_i[4], l_i[4], acc[4][8];
#pragma unroll
    for (int i = 0; i < 4; i++) {
        m_i[i] = -1e30f;
        l_i[i] = 0.f;
        qdoc[i] = doc[q0 + ty * 4 + i];
#pragma unroll
        for (int j = 0; j < 8; j++) acc[i][j] = 0.f;
    }
    __syncthreads();

    for (int t = 0; t <= qb; ++t) {
        const int k0 = t * 64;
        for (int idx = tid; idx < 64 * 128; idx += 256) {
            int r = idx >> 7, d = idx & 127;
            size_t src = ((size_t)(k0 + r) * NKV + kvh) * HD + d;
            Ks[r * QS_STRIDE + d] = g_k[src];
            Vs[r * VS_STRIDE + d] = g_v[src];
        }
        if (tid < 64) kdoc[tid] = doc[k0 + tid];
        __syncthreads();

        // scores: S = Q * K^T  (4x4 per thread over 64x64 tile)
        float s[4][4];
#pragma unroll
        for (int i = 0; i < 4; i++)
#pragma unroll
            for (int j = 0; j < 4; j++) s[i][j] = 0.f;

#pragma unroll 8
        for (int kk = 0; kk < 128; kk++) {
            float ra[4], rb[4];
#pragma unroll
            for (int i = 0; i < 4; i++) ra[i] = Qs[(ty * 4 + i) * QS_STRIDE + kk];
#pragma unroll
            for (int j = 0; j < 4; j++) rb[j] = Ks[(tx * 4 + j) * QS_STRIDE + kk];
#pragma unroll
            for (int i = 0; i < 4; i++)
#pragma unroll
                for (int j = 0; j < 4; j++)
                    s[i][j] = fmaf(ra[i], rb[j], s[i][j]);
        }

        // mask + scale
#pragma unroll
        for (int i = 0; i < 4; i++) {
            int qrow = q0 + ty * 4 + i;
#pragma unroll
            for (int j = 0; j < 4; j++) {
                int kcol = k0 + tx * 4 + j;
                bool valid = (qrow >= kcol) && (qdoc[i] == kdoc[tx * 4 + j]);
                s[i][j] = valid ? s[i][j] * SOFT_SCALE : -1e30f;
            }
        }

        // online softmax update (rows split across 16 lanes of a half-warp)
        float newm[4], corr[4];
#pragma unroll
        for (int i = 0; i < 4; i++) {
            float mx = fmaxf(fmaxf(s[i][0], s[i][1]), fmaxf(s[i][2], s[i][3]));
#pragma unroll
            for (int off = 1; off < 16; off <<= 1)
                mx = fmaxf(mx, __shfl_xor_sync(0xffffffffu, mx, off));
            newm[i] = fmaxf(m_i[i], mx);
            corr[i] = __expf(m_i[i] - newm[i]);
            m_i[i]  = newm[i];
        }

#pragma unroll
        for (int i = 0; i < 4; i++) {
            float rs = 0.f;
#pragma unroll
            for (int j = 0; j < 4; j++) {
                float p = (s[i][j] > -1e29f) ? __expf(s[i][j] - newm[i]) : 0.f;
                Ps[(ty * 4 + i) * PS_STRIDE + tx * 4 + j] = p;
                rs += p;
            }
#pragma unroll
            for (int off = 1; off < 16; off <<= 1)
                rs += __shfl_xor_sync(0xffffffffu, rs, off);
            l_i[i] = l_i[i] * corr[i] + rs;
        }
        __syncthreads();   // Ps fully written

        // O accum: rescale then O += P * V  (4x8 per thread over 64x128)
#pragma unroll
        for (int i = 0; i < 4; i++)
#pragma unroll
            for (int j = 0; j < 8; j++) acc[i][j] *= corr[i];

#pragma unroll 4
        for (int kc = 0; kc < 64; kc++) {
            float rp[4];
#pragma unroll
            for (int i = 0; i < 4; i++) rp[i] = Ps[(ty * 4 + i) * PS_STRIDE + kc];
            float4 v0 = *(const float4*)(&Vs[kc * VS_STRIDE + tx * 8]);
            float4 v1 = *(const float4*)(&Vs[kc * VS_STRIDE + tx * 8 + 4]);
            float rv[8] = {v0.x, v0.y, v0.z, v0.w, v1.x, v1.y, v1.z, v1.w};
#pragma unroll
            for (int i = 0; i < 4; i++)
#pragma unroll
                for (int j = 0; j < 8; j++)
                    acc[i][j] = fmaf(rp[i], rv[j], acc[i][j]);
        }
        __syncthreads();   // done with Ks/Vs/Ps this tile
    }

    // normalize and write
#pragma unroll
    for (int i = 0; i < 4; i++) {
        float inv = 1.f / l_i[i];
        int row = q0 + ty * 4 + i;
#pragma unroll
        for (int j = 0; j < 8; j++)
            g_o[((size_t)row * NH + head) * HD + tx * 8 + j] = acc[i][j] * inv;
    }
}

// ---------------- launch -----------------------------------------------------
extern "C" void kernel_launch(void* const* d_in, const int* in_sizes, int n_in,
                              void* d_out, int out_size)
{
    const float* hidden = (const float*)d_in[0];
    const float* cosT   = (const float*)d_in[1];
    const float* sinT   = (const float*)d_in[2];
    const int*   doc    = (const int*)  d_in[3];
    // d_in[4] = position_ids (unused; rope tables precomputed)
    const float* Wq = (const float*)d_in[5];
    const float* bq = (const float*)d_in[6];
    const float* Wk = (const float*)d_in[7];
    const float* bk = (const float*)d_in[8];
    const float* Wv = (const float*)d_in[9];
    const float* bv = (const float*)d_in[10];
    const float* Wo = (const float*)d_in[11];
    float* out = (float*)d_out;

    float *qp, *kp, *vp, *op;
    cudaGetSymbolAddress((void**)&qp, g_q);
    cudaGetSymbolAddress((void**)&kp, g_k);
    cudaGetSymbolAddress((void**)&vp, g_v);
    cudaGetSymbolAddress((void**)&op, g_o);

    // QKV projections
    sgemm_bias<<<dim3(NH * HD / 128, SEQ / 128), 256>>>(hidden, Wq, bq, qp, SEQ, NH * HD, HID);
    sgemm_bias<<<dim3(NKV * HD / 128, SEQ / 128), 256>>>(hidden, Wk, bk, kp, SEQ, NKV * HD, HID);
    sgemm_bias<<<dim3(NKV * HD / 128, SEQ / 128), 256>>>(hidden, Wv, bv, vp, SEQ, NKV * HD, HID);

    // RoPE in place
    rope_kernel<<<SEQ, HD>>>(cosT, sinT);

    // Flash attention
    cudaFuncSetAttribute(flash_kernel, cudaFuncAttributeMaxDynamicSharedMemorySize, FLASH_SMEM);
    flash_kernel<<<dim3(SEQ / 64, NH), 256, FLASH_SMEM>>>(doc);

    // Output projection
    sgemm_bias<<<dim3(HID / 128, SEQ / 128), 256>>>(op, Wo, nullptr, out, SEQ, HID, HID);
}

// round 2
// speedup vs baseline: 2.7883x; 2.7883x over previous
#include <cuda_runtime.h>
#include <math.h>
#include <stdint.h>

#define SEQ 2048
#define HID 3584
#define NH 28
#define NKV 4
#define GRP 7
#define HD 128
#define SOFT_SCALE 0.08838834764831845f   // 1/sqrt(128)

// ---------------- scratch (static device globals; no runtime allocation) ----
__device__ float g_q[SEQ * NH * HD];
__device__ float g_k[SEQ * NKV * HD];
__device__ float g_v[SEQ * NKV * HD];
__device__ float g_o[SEQ * NH * HD];

// ---------------- helpers ----------------------------------------------------
__device__ __forceinline__ uint32_t f2tf(float f) {
    uint32_t u;
    asm("cvt.rna.tf32.f32 %0, %1;" : "=r"(u) : "f"(f));
    return u;
}

__device__ __forceinline__ void mma_tf32(float* c, const uint32_t* a, const uint32_t* b) {
    asm volatile(
        "mma.sync.aligned.m16n8k8.row.col.f32.tf32.tf32.f32 "
        "{%0,%1,%2,%3}, {%4,%5,%6,%7}, {%8,%9}, {%0,%1,%2,%3};"
        : "+f"(c[0]), "+f"(c[1]), "+f"(c[2]), "+f"(c[3])
        : "r"(a[0]), "r"(a[1]), "r"(a[2]), "r"(a[3]), "r"(b[0]), "r"(b[1]));
}

// ---------------- TF32 tensor-core GEMM: C = A[M,K] * B[N,K]^T + bias --------
// 128x128 block, 256 threads (8 warps), warp tile 64x32, BK=16.
#define GSTR 20   // smem row stride (16 + 4 pad) -> conflict-free frag loads

__global__ __launch_bounds__(256) void gemm_tf32(
    const float* __restrict__ A, const float* __restrict__ B,
    const float* __restrict__ bias, float* __restrict__ C,
    int M, int N, int K)
{
    __shared__ uint32_t As[128 * GSTR];
    __shared__ uint32_t Bs[128 * GSTR];

    const int tid  = threadIdx.x;
    const int warp = tid >> 5, lane = tid & 31;
    const int g = lane >> 2, tg = lane & 3;
    const int wm = (warp >> 2) * 64;   // warp m offset (0/64)
    const int wn = (warp & 3) * 32;    // warp n offset (0..96)
    const int bx = blockIdx.x, by = blockIdx.y;

    float acc[16][4];
#pragma unroll
    for (int i = 0; i < 16; i++)
#pragma unroll
        for (int j = 0; j < 4; j++) acc[i][j] = 0.f;

    for (int k0 = 0; k0 < K; k0 += 16) {
#pragma unroll
        for (int l = 0; l < 2; l++) {
            int f   = tid + l * 256;        // 0..511
            int row = f >> 2;
            int kc  = (f & 3) * 4;
            float4 av = *(const float4*)(A + (size_t)(by * 128 + row) * K + k0 + kc);
            float4 bv = *(const float4*)(B + (size_t)(bx * 128 + row) * K + k0 + kc);
            uint4 at = make_uint4(f2tf(av.x), f2tf(av.y), f2tf(av.z), f2tf(av.w));
            uint4 bt = make_uint4(f2tf(bv.x), f2tf(bv.y), f2tf(bv.z), f2tf(bv.w));
            *(uint4*)(&As[row * GSTR + kc]) = at;
            *(uint4*)(&Bs[row * GSTR + kc]) = bt;
        }
        __syncthreads();

#pragma unroll
        for (int kk = 0; kk < 16; kk += 8) {
            uint32_t a[4][4], bf[4][2];
#pragma unroll
            for (int mt = 0; mt < 4; mt++) {
                int r = wm + mt * 16;
                a[mt][0] = As[(r + g) * GSTR + kk + tg];
                a[mt][1] = As[(r + 8 + g) * GSTR + kk + tg];
                a[mt][2] = As[(r + g) * GSTR + kk + 4 + tg];
                a[mt][3] = As[(r + 8 + g) * GSTR + kk + 4 + tg];
            }
#pragma unroll
            for (int nt = 0; nt < 4; nt++) {
                int c = wn + nt * 8;
                bf[nt][0] = Bs[(c + g) * GSTR + kk + tg];
                bf[nt][1] = Bs[(c + g) * GSTR + kk + 4 + tg];
            }
#pragma unroll
            for (int mt = 0; mt < 4; mt++)
#pragma unroll
                for (int nt = 0; nt < 4; nt++)
                    mma_tf32(acc[mt * 4 + nt], a[mt], bf[nt]);
        }
        __syncthreads();
    }

#pragma unroll
    for (int mt = 0; mt < 4; mt++) {
#pragma unroll
        for (int nt = 0; nt < 4; nt++) {
            int r0 = by * 128 + wm + mt * 16 + g;
            int c0 = bx * 128 + wn + nt * 8 + 2 * tg;
            float b0 = bias ? bias[c0] : 0.f;
            float b1 = bias ? bias[c0 + 1] : 0.f;
            float* ca = acc[mt * 4 + nt];
            *(float2*)(&C[(size_t)r0 * N + c0])       = make_float2(ca[0] + b0, ca[1] + b1);
            *(float2*)(&C[(size_t)(r0 + 8) * N + c0]) = make_float2(ca[2] + b0, ca[3] + b1);
        }
    }
}

// ---------------- RoPE (in place on g_q, g_k) --------------------------------
__global__ void rope_kernel(const float* __restrict__ cosT,
                            const float* __restrict__ sinT)
{
    const int s = blockIdx.x;
    const int d = threadIdx.x;
    const float c  = cosT[s * HD + d];
    const float sn = sinT[s * HD + d];

    for (int h = 0; h < NH; h++) {
        float* row = g_q + ((size_t)s * NH + h) * HD;
        float x  = row[d];
        float xo = row[d ^ 64];
        float r  = (d < 64) ? -xo : xo;
        __syncthreads();
        row[d] = x * c + r * sn;
        __syncthreads();
    }
    for (int h = 0; h < NKV; h++) {
        float* row = g_k + ((size_t)s * NKV + h) * HD;
        float x  = row[d];
        float xo = row[d ^ 64];
        float r  = (d < 64) ? -xo : xo;
        __syncthreads();
        row[d] = x * c + r * sn;
        __syncthreads();
    }
}

// ---------------- Flash attention (TF32 mma, fp32 softmax) -------------------
// BQ=128, BKV=64. 256 threads = 8 warps; warp owns 16 full query rows.
#define QSTR 132
#define KSTR 132
#define VSTR 136
#define PSTR 68
#define FLASH_SMEM ((128*QSTR + 64*KSTR + 64*VSTR + 128*PSTR) * 4 + 64 * 4)

__global__ __launch_bounds__(256) void flash_kernel(const int* __restrict__ doc)
{
    extern __shared__ uint32_t fsm[];
    uint32_t* Qs = fsm;                  // [128][QSTR] tf32
    uint32_t* Ks = Qs + 128 * QSTR;      // [64][KSTR]  tf32 (row = key, col = d)
    uint32_t* Vs = Ks + 64 * KSTR;       // [64][VSTR]  tf32 (row = key, col = d)
    uint32_t* Ps = Vs + 64 * VSTR;       // [128][PSTR] tf32
    int* kdoc = (int*)(Ps + 128 * PSTR);

    const int qb = blockIdx.x, head = blockIdx.y;
    const int kvh = head / GRP;
    const int q0 = qb * 128;
    const int tid = threadIdx.x;
    const int warp = tid >> 5, lane = tid & 31;
    const int g = lane >> 2, tg = lane & 3;
    const int m0 = warp * 16;

    // load + convert Q tile
    for (int f = tid; f < 128 * 32; f += 256) {
        int row = f >> 5, c4 = (f & 31) * 4;
        float4 v = *(const float4*)(g_q + ((size_t)(q0 + row) * NH + head) * HD + c4);
        *(uint4*)(&Qs[row * QSTR + c4]) = make_uint4(f2tf(v.x), f2tf(v.y), f2tf(v.z), f2tf(v.w));
    }

    const int qr0 = q0 + m0 + g, qr1 = qr0 + 8;
    const int qd0 = doc[qr0], qd1 = doc[qr1];
    float mi0 = -1e30f, mi1 = -1e30f, li0 = 0.f, li1 = 0.f;
    float o[16][4];
#pragma unroll
    for (int i = 0; i < 16; i++)
#pragma unroll
        for (int j = 0; j < 4; j++) o[i][j] = 0.f;
    __syncthreads();

    const int tmax = 2 * qb + 1;
    for (int t = 0; t <= tmax; t++) {
        const int k0 = t * 64;
        for (int f = tid; f < 64 * 32; f += 256) {
            int row = f >> 5, c4 = (f & 31) * 4;
            size_t src = ((size_t)(k0 + row) * NKV + kvh) * HD + c4;
            float4 kv = *(const float4*)(g_k + src);
            float4 vv = *(const float4*)(g_v + src);
            *(uint4*)(&Ks[row * KSTR + c4]) = make_uint4(f2tf(kv.x), f2tf(kv.y), f2tf(kv.z), f2tf(kv.w));
            *(uint4*)(&Vs[row * VSTR + c4]) = make_uint4(f2tf(vv.x), f2tf(vv.y), f2tf(vv.z), f2tf(vv.w));
        }
        if (tid < 64) kdoc[tid] = doc[k0 + tid];
        __syncthreads();

        // scores: warp computes m16 x n64 x k128
        float s[8][4];
#pragma unroll
        for (int i = 0; i < 8; i++)
#pragma unroll
            for (int j = 0; j < 4; j++) s[i][j] = 0.f;

#pragma unroll
        for (int kk = 0; kk < 128; kk += 8) {
            uint32_t a[4];
            a[0] = Qs[(m0 + g) * QSTR + kk + tg];
            a[1] = Qs[(m0 + 8 + g) * QSTR + kk + tg];
            a[2] = Qs[(m0 + g) * QSTR + kk + 4 + tg];
            a[3] = Qs[(m0 + 8 + g) * QSTR + kk + 4 + tg];
#pragma unroll
            for (int nt = 0; nt < 8; nt++) {
                uint32_t bf[2];
                bf[0] = Ks[(nt * 8 + g) * KSTR + kk + tg];
                bf[1] = Ks[(nt * 8 + g) * KSTR + kk + 4 + tg];
                mma_tf32(s[nt], a, bf);
            }
        }

        // mask + scale
        float mx0 = -1e30f, mx1 = -1e30f;
#pragma unroll
        for (int nt = 0; nt < 8; nt++) {
            int c0 = k0 + nt * 8 + 2 * tg;
            int d0 = kdoc[nt * 8 + 2 * tg];
            int d1 = kdoc[nt * 8 + 2 * tg + 1];
            s[nt][0] = (qr0 >= c0     && qd0 == d0) ? s[nt][0] * SOFT_SCALE : -1e30f;
            s[nt][1] = (qr0 >= c0 + 1 && qd0 == d1) ? s[nt][1] * SOFT_SCALE : -1e30f;
            s[nt][2] = (qr1 >= c0     && qd1 == d0) ? s[nt][2] * SOFT_SCALE : -1e30f;
            s[nt][3] = (qr1 >= c0 + 1 && qd1 == d1) ? s[nt][3] * SOFT_SCALE : -1e30f;
            mx0 = fmaxf(mx0, fmaxf(s[nt][0], s[nt][1]));
            mx1 = fmaxf(mx1, fmaxf(s[nt][2], s[nt][3]));
        }
        mx0 = fmaxf(mx0, __shfl_xor_sync(0xffffffffu, mx0, 1));
        mx0 = fmaxf(mx0, __shfl_xor_sync(0xffffffffu, mx0, 2));
        mx1 = fmaxf(mx1, __shfl_xor_sync(0xffffffffu, mx1, 1));
        mx1 = fmaxf(mx1, __shfl_xor_sync(0xffffffffu, mx1, 2));

        float nm0 = fmaxf(mi0, mx0), nm1 = fmaxf(mi1, mx1);
        float cr0 = __expf(mi0 - nm0), cr1 = __expf(mi1 - nm1);
        mi0 = nm0; mi1 = nm1;
#pragma unroll
        for (int nt = 0; nt < 16; nt++) {
            o[nt][0] *= cr0; o[nt][1] *= cr0;
            o[nt][2] *= cr1; o[nt][3] *= cr1;
        }

        float rs0 = 0.f, rs1 = 0.f;
#pragma unroll
        for (int nt = 0; nt < 8; nt++) {
            float p0 = (s[nt][0] > -1e29f) ? __expf(s[nt][0] - nm0) : 0.f;
            float p1 = (s[nt][1] > -1e29f) ? __expf(s[nt][1] - nm0) : 0.f;
            float p2 = (s[nt][2] > -1e29f) ? __expf(s[nt][2] - nm1) : 0.f;
            float p3 = (s[nt][3] > -1e29f) ? __expf(s[nt][3] - nm1) : 0.f;
            rs0 += p0 + p1; rs1 += p2 + p3;
            int c = nt * 8 + 2 * tg;
            Ps[(m0 + g) * PSTR + c]         = f2tf(p0);
            Ps[(m0 + g) * PSTR + c + 1]     = f2tf(p1);
            Ps[(m0 + 8 + g) * PSTR + c]     = f2tf(p2);
            Ps[(m0 + 8 + g) * PSTR + c + 1] = f2tf(p3);
        }
        rs0 += __shfl_xor_sync(0xffffffffu, rs0, 1);
        rs0 += __shfl_xor_sync(0xffffffffu, rs0, 2);
        rs1 += __shfl_xor_sync(0xffffffffu, rs1, 1);
        rs1 += __shfl_xor_sync(0xffffffffu, rs1, 2);
        li0 = li0 * cr0 + rs0;
        li1 = li1 * cr1 + rs1;
        __syncwarp();   // Ps rows are warp-private; order STS -> LDS

        // O += P * V : warp m16 x n128 x k64
#pragma unroll
        for (int kk = 0; kk < 64; kk += 8) {
            uint32_t a[4];
            a[0] = Ps[(m0 + g) * PSTR + kk + tg];
            a[1] = Ps[(m0 + 8 + g) * PSTR + kk + tg];
            a[2] = Ps[(m0 + g) * PSTR + kk + 4 + tg];
            a[3] = Ps[(m0 + 8 + g) * PSTR + kk + 4 + tg];
#pragma unroll
            for (int nt = 0; nt < 16; nt++) {
                uint32_t bf[2];
                bf[0] = Vs[(kk + tg) * VSTR + nt * 8 + g];
                bf[1] = Vs[(kk + 4 + tg) * VSTR + nt * 8 + g];
                mma_tf32(o[nt], a, bf);
            }
        }
        __syncthreads();   // protect Ks/Vs before next tile's load
    }

    // normalize + write
    float inv0 = 1.f / li0, inv1 = 1.f / li1;
#pragma unroll
    for (int nt = 0; nt < 16; nt++) {
        int c = nt * 8 + 2 * tg;
        *(float2*)(&g_o[((size_t)qr0 * NH + head) * HD + c]) =
            make_float2(o[nt][0] * inv0, o[nt][1] * inv0);
        *(float2*)(&g_o[((size_t)qr1 * NH + head) * HD + c]) =
            make_float2(o[nt][2] * inv1, o[nt][3] * inv1);
    }
}

// ---------------- launch -----------------------------------------------------
extern "C" void kernel_launch(void* const* d_in, const int* in_sizes, int n_in,
                              void* d_out, int out_size)
{
    const float* hidden = (const float*)d_in[0];
    const float* cosT   = (const float*)d_in[1];
    const float* sinT   = (const float*)d_in[2];
    const int*   doc    = (const int*)  d_in[3];
    const float* Wq = (const float*)d_in[5];
    const float* bq = (const float*)d_in[6];
    const float* Wk = (const float*)d_in[7];
    const float* bk = (const float*)d_in[8];
    const float* Wv = (const float*)d_in[9];
    const float* bv = (const float*)d_in[10];
    const float* Wo = (const float*)d_in[11];
    float* out = (float*)d_out;

    float *qp, *kp, *vp, *op;
    cudaGetSymbolAddress((void**)&qp, g_q);
    cudaGetSymbolAddress((void**)&kp, g_k);
    cudaGetSymbolAddress((void**)&vp, g_v);
    cudaGetSymbolAddress((void**)&op, g_o);

    // QKV projections (tensor core TF32)
    gemm_tf32<<<dim3(NH * HD / 128, SEQ / 128), 256>>>(hidden, Wq, bq, qp, SEQ, NH * HD, HID);
    gemm_tf32<<<dim3(NKV * HD / 128, SEQ / 128), 256>>>(hidden, Wk, bk, kp, SEQ, NKV * HD, HID);
    gemm_tf32<<<dim3(NKV * HD / 128, SEQ / 128), 256>>>(hidden, Wv, bv, vp, SEQ, NKV * HD, HID);

    // RoPE in place
    rope_kernel<<<SEQ, HD>>>(cosT, sinT);

    // Flash attention (tensor core TF32)
    cudaFuncSetAttribute(flash_kernel, cudaFuncAttributeMaxDynamicSharedMemorySize, FLASH_SMEM);
    flash_kernel<<<dim3(SEQ / 128, NH), 256, FLASH_SMEM>>>(doc);

    // Output projection
    gemm_tf32<<<dim3(HID / 128, SEQ / 128), 256>>>(op, Wo, nullptr, out, SEQ, HID, HID);
}

// round 3
// speedup vs baseline: 4.1154x; 1.4759x over previous
#include <cuda_runtime.h>
#include <math.h>
#include <stdint.h>

#define SEQ 2048
#define HID 3584
#define NH 28
#define NKV 4
#define GRP 7
#define HD 128
#define SOFT_SCALE 0.08838834764831845f   // 1/sqrt(128)

// ---------------- scratch (static device globals; no runtime allocation) ----
__device__ float g_q[SEQ * NH * HD];   // raw QKV projections (rope fused later)
__device__ float g_k[SEQ * NKV * HD];
__device__ float g_v[SEQ * NKV * HD];
__device__ float g_o[SEQ * NH * HD];

// ---------------- helpers ----------------------------------------------------
__device__ __forceinline__ uint32_t f2tf(float f) {
    uint32_t u;
    asm("cvt.rna.tf32.f32 %0, %1;" : "=r"(u) : "f"(f));
    return u;
}

__device__ __forceinline__ void mma_tf32(float* c, const uint32_t* a, const uint32_t* b) {
    asm volatile(
        "mma.sync.aligned.m16n8k8.row.col.f32.tf32.tf32.f32 "
        "{%0,%1,%2,%3}, {%4,%5,%6,%7}, {%8,%9}, {%0,%1,%2,%3};"
        : "+f"(c[0]), "+f"(c[1]), "+f"(c[2]), "+f"(c[3])
        : "r"(a[0]), "r"(a[1]), "r"(a[2]), "r"(a[3]), "r"(b[0]), "r"(b[1]));
}

__device__ __forceinline__ uint32_t smem_u32(const void* p) {
    return (uint32_t)__cvta_generic_to_shared(p);
}
__device__ __forceinline__ void cp16(uint32_t s, const void* g) {
    asm volatile("cp.async.cg.shared.global [%0], [%1], 16;" :: "r"(s), "l"(g));
}

// ---------------- TF32 tensor GEMM body: C = A[M,K]*B[N,K]^T + bias ----------
// 128x128 block, 256 threads (8 warps), warp tile 64x32, BK=16,
// cp.async double-buffered (raw fp32 in smem; tf32 cvt at fragment load).
#define GSTR 20            // floats per smem row (16 + 4 pad): conflict-free
#define GSTAGE (128 * GSTR)

__device__ __forceinline__ void gemm_body(
    const float* __restrict__ A, const float* __restrict__ B,
    const float* __restrict__ bias, float* __restrict__ C,
    int N, int K, int bx, int by, float* As, float* Bs)
{
    const int tid  = threadIdx.x;
    const int warp = tid >> 5, lane = tid & 31;
    const int g = lane >> 2, tg = lane & 3;
    const int wm = (warp >> 2) * 64;
    const int wn = (warp & 3) * 32;

    // loader mapping: 512 float4 per matrix per tile, 2 per thread
    const int row0 = tid >> 2,        kc0 = (tid & 3) * 4;
    const int row1 = (tid + 256) >> 2, kc1 = ((tid + 256) & 3) * 4;

    const float* Ap0 = A + (size_t)(by * 128 + row0) * K + kc0;
    const float* Ap1 = A + (size_t)(by * 128 + row1) * K + kc1;
    const float* Bp0 = B + (size_t)(bx * 128 + row0) * K + kc0;
    const float* Bp1 = B + (size_t)(bx * 128 + row1) * K + kc1;
    const uint32_t sA0 = smem_u32(As + row0 * GSTR + kc0);
    const uint32_t sA1 = smem_u32(As + row1 * GSTR + kc1);
    const uint32_t sB0 = smem_u32(Bs + row0 * GSTR + kc0);
    const uint32_t sB1 = smem_u32(Bs + row1 * GSTR + kc1);

    float acc[16][4];
#pragma unroll
    for (int i = 0; i < 16; i++)
#pragma unroll
        for (int j = 0; j < 4; j++) acc[i][j] = 0.f;

    // prefetch tile 0 -> stage 0
    cp16(sA0, Ap0); cp16(sA1, Ap1);
    cp16(sB0, Bp0); cp16(sB1, Bp1);
    asm volatile("cp.async.commit_group;");

    const int T = K / 16;
    for (int t = 0; t < T; t++) {
        if (t + 1 < T) {
            const int k1 = (t + 1) * 16;
            const uint32_t so = (uint32_t)(((t + 1) & 1) * GSTAGE * 4);
            cp16(sA0 + so, Ap0 + k1); cp16(sA1 + so, Ap1 + k1);
            cp16(sB0 + so, Bp0 + k1); cp16(sB1 + so, Bp1 + k1);
            asm volatile("cp.async.commit_group;");
            asm volatile("cp.async.wait_group 1;");
        } else {
            asm volatile("cp.async.wait_group 0;");
        }
        __syncthreads();

        const float* as = As + (t & 1) * GSTAGE;
        const float* bs = Bs + (t & 1) * GSTAGE;
#pragma unroll
        for (int kk = 0; kk < 16; kk += 8) {
            uint32_t a[4][4], bf[4][2];
#pragma unroll
            for (int mt = 0; mt < 4; mt++) {
                int r = wm + mt * 16;
                a[mt][0] = f2tf(as[(r + g) * GSTR + kk + tg]);
                a[mt][1] = f2tf(as[(r + 8 + g) * GSTR + kk + tg]);
                a[mt][2] = f2tf(as[(r + g) * GSTR + kk + 4 + tg]);
                a[mt][3] = f2tf(as[(r + 8 + g) * GSTR + kk + 4 + tg]);
            }
#pragma unroll
            for (int nt = 0; nt < 4; nt++) {
                int c = wn + nt * 8;
                bf[nt][0] = f2tf(bs[(c + g) * GSTR + kk + tg]);
                bf[nt][1] = f2tf(bs[(c + g) * GSTR + kk + 4 + tg]);
            }
#pragma unroll
            for (int mt = 0; mt < 4; mt++)
#pragma unroll
                for (int nt = 0; nt < 4; nt++)
                    mma_tf32(acc[mt * 4 + nt], a[mt], bf[nt]);
        }
        __syncthreads();
    }

#pragma unroll
    for (int mt = 0; mt < 4; mt++) {
#pragma unroll
        for (int nt = 0; nt < 4; nt++) {
            int r0 = by * 128 + wm + mt * 16 + g;
            int c0 = bx * 128 + wn + nt * 8 + 2 * tg;
            float b0 = bias ? bias[c0] : 0.f;
            float b1 = bias ? bias[c0 + 1] : 0.f;
            float* ca = acc[mt * 4 + nt];
            *(float2*)(&C[(size_t)r0 * N + c0])       = make_float2(ca[0] + b0, ca[1] + b1);
            *(float2*)(&C[(size_t)(r0 + 8) * N + c0]) = make_float2(ca[2] + b0, ca[3] + b1);
        }
    }
}

// Fused QKV projection: bx<28 -> Q, 28..31 -> K, 32..35 -> V
__global__ __launch_bounds__(256) void gemm_qkv(
    const float* __restrict__ hidden,
    const float* __restrict__ Wq, const float* __restrict__ bq,
    const float* __restrict__ Wk, const float* __restrict__ bk,
    const float* __restrict__ Wv, const float* __restrict__ bv,
    float* __restrict__ q, float* __restrict__ k, float* __restrict__ v)
{
    __shared__ float As[2 * GSTAGE];
    __shared__ float Bs[2 * GSTAGE];
    const int bx = blockIdx.x, by = blockIdx.y;
    if (bx < 28)
        gemm_body(hidden, Wq, bq, q, NH * HD, HID, bx, by, As, Bs);
    else if (bx < 32)
        gemm_body(hidden, Wk, bk, k, NKV * HD, HID, bx - 28, by, As, Bs);
    else
        gemm_body(hidden, Wv, bv, v, NKV * HD, HID, bx - 32, by, As, Bs);
}

__global__ __launch_bounds__(256) void gemm_out(
    const float* __restrict__ A, const float* __restrict__ Wo,
    float* __restrict__ C)
{
    __shared__ float As[2 * GSTAGE];
    __shared__ float Bs[2 * GSTAGE];
    gemm_body(A, Wo, nullptr, C, HID, HID, blockIdx.x, blockIdx.y, As, Bs);
}

// ---------------- Flash attention (TF32 mma, fp32 softmax, fused RoPE) -------
// BQ=128, BKV=64. 256 threads = 8 warps; warp owns 16 full query rows.
#define QSTR 132
#define KSTR 132
#define VSTR 136
#define PSTR 68
#define FLASH_SMEM ((128*QSTR + 64*KSTR + 64*VSTR + 128*PSTR) * 4 + 64 * 4)

__global__ __launch_bounds__(256) void flash_kernel(
    const int* __restrict__ doc,
    const float* __restrict__ cosT, const float* __restrict__ sinT)
{
    extern __shared__ uint32_t fsm[];
    uint32_t* Qs = fsm;                  // [128][QSTR] tf32 (rope applied)
    uint32_t* Ks = Qs + 128 * QSTR;      // [64][KSTR]  tf32 (rope applied)
    uint32_t* Vs = Ks + 64 * KSTR;       // [64][VSTR]  tf32
    uint32_t* Ps = Vs + 64 * VSTR;       // [128][PSTR] tf32
    int* kdoc = (int*)(Ps + 128 * PSTR);

    const int qb = gridDim.x - 1 - blockIdx.x;   // longest blocks first
    const int head = blockIdx.y;
    const int kvh = head / GRP;
    const int q0 = qb * 128;
    const int tid = threadIdx.x;
    const int warp = tid >> 5, lane = tid & 31;
    const int g = lane >> 2, tg = lane & 3;
    const int m0 = warp * 16;

    // load Q tile + RoPE + tf32 convert
    for (int f = tid; f < 128 * 32; f += 256) {
        int row = f >> 5, c4 = (f & 31) * 4;
        int s = q0 + row;
        const float* base = g_q + ((size_t)s * NH + head) * HD;
        float4 x  = *(const float4*)(base + c4);
        float4 xo = *(const float4*)(base + (c4 ^ 64));
        float4 cc = *(const float4*)(cosT + (size_t)s * HD + c4);
        float4 sn = *(const float4*)(sinT + (size_t)s * HD + c4);
        float sg = (c4 < 64) ? -1.f : 1.f;
        *(uint4*)(&Qs[row * QSTR + c4]) = make_uint4(
            f2tf(fmaf(sg * xo.x, sn.x, x.x * cc.x)),
            f2tf(fmaf(sg * xo.y, sn.y, x.y * cc.y)),
            f2tf(fmaf(sg * xo.z, sn.z, x.z * cc.z)),
            f2tf(fmaf(sg * xo.w, sn.w, x.w * cc.w)));
    }

    const int qr0 = q0 + m0 + g, qr1 = qr0 + 8;
    const int qd0 = doc[qr0], qd1 = doc[qr1];
    float mi0 = -1e30f, mi1 = -1e30f, li0 = 0.f, li1 = 0.f;
    float o[16][4];
#pragma unroll
    for (int i = 0; i < 16; i++)
#pragma unroll
        for (int j = 0; j < 4; j++) o[i][j] = 0.f;
    __syncthreads();

    const int tmax = 2 * qb + 1;
    for (int t = 0; t <= tmax; t++) {
        const int k0 = t * 64;
        // load K (rope) + V tiles, convert to tf32
        for (int f = tid; f < 64 * 32; f += 256) {
            int row = f >> 5, c4 = (f & 31) * 4;
            int s = k0 + row;
            const float* kb = g_k + ((size_t)s * NKV + kvh) * HD;
            float4 x  = *(const float4*)(kb + c4);
            float4 xo = *(const float4*)(kb + (c4 ^ 64));
            float4 cc = *(const float4*)(cosT + (size_t)s * HD + c4);
            float4 sn = *(const float4*)(sinT + (size_t)s * HD + c4);
            float sg = (c4 < 64) ? -1.f : 1.f;
            *(uint4*)(&Ks[row * KSTR + c4]) = make_uint4(
                f2tf(fmaf(sg * xo.x, sn.x, x.x * cc.x)),
                f2tf(fmaf(sg * xo.y, sn.y, x.y * cc.y)),
                f2tf(fmaf(sg * xo.z, sn.z, x.z * cc.z)),
                f2tf(fmaf(sg * xo.w, sn.w, x.w * cc.w)));
            float4 vv = *(const float4*)(g_v + ((size_t)s * NKV + kvh) * HD + c4);
            *(uint4*)(&Vs[row * VSTR + c4]) =
                make_uint4(f2tf(vv.x), f2tf(vv.y), f2tf(vv.z), f2tf(vv.w));
        }
        if (tid < 64) kdoc[tid] = doc[k0 + tid];
        __syncthreads();

        // scores: warp computes m16 x n64 x k128
        float s[8][4];
#pragma unroll
        for (int i = 0; i < 8; i++)
#pragma unroll
            for (int j = 0; j < 4; j++) s[i][j] = 0.f;

#pragma unroll
        for (int kk = 0; kk < 128; kk += 8) {
            uint32_t a[4];
            a[0] = Qs[(m0 + g) * QSTR + kk + tg];
            a[1] = Qs[(m0 + 8 + g) * QSTR + kk + tg];
            a[2] = Qs[(m0 + g) * QSTR + kk + 4 + tg];
            a[3] = Qs[(m0 + 8 + g) * QSTR + kk + 4 + tg];
#pragma unroll
            for (int nt = 0; nt < 8; nt++) {
                uint32_t bf[2];
                bf[0] = Ks[(nt * 8 + g) * KSTR + kk + tg];
                bf[1] = Ks[(nt * 8 + g) * KSTR + kk + 4 + tg];
                mma_tf32(s[nt], a, bf);
            }
        }

        // mask + scale
        float mx0 = -1e30f, mx1 = -1e30f;
#pragma unroll
        for (int nt = 0; nt < 8; nt++) {
            int c0 = k0 + nt * 8 + 2 * tg;
            int d0 = kdoc[nt * 8 + 2 * tg];
            int d1 = kdoc[nt * 8 + 2 * tg + 1];
            s[nt][0] = (qr0 >= c0     && qd0 == d0) ? s[nt][0] * SOFT_SCALE : -1e30f;
            s[nt][1] = (qr0 >= c0 + 1 && qd0 == d1) ? s[nt][1] * SOFT_SCALE : -1e30f;
            s[nt][2] = (qr1 >= c0     && qd1 == d0) ? s[nt][2] * SOFT_SCALE : -1e30f;
            s[nt][3] = (qr1 >= c0 + 1 && qd1 == d1) ? s[nt][3] * SOFT_SCALE : -1e30f;
            mx0 = fmaxf(mx0, fmaxf(s[nt][0], s[nt][1]));
            mx1 = fmaxf(mx1, fmaxf(s[nt][2], s[nt][3]));
        }
        mx0 = fmaxf(mx0, __shfl_xor_sync(0xffffffffu, mx0, 1));
        mx0 = fmaxf(mx0, __shfl_xor_sync(0xffffffffu, mx0, 2));
        mx1 = fmaxf(mx1, __shfl_xor_sync(0xffffffffu, mx1, 1));
        mx1 = fmaxf(mx1, __shfl_xor_sync(0xffffffffu, mx1, 2));

        float nm0 = fmaxf(mi0, mx0), nm1 = fmaxf(mi1, mx1);
        float cr0 = __expf(mi0 - nm0), cr1 = __expf(mi1 - nm1);
        mi0 = nm0; mi1 = nm1;
#pragma unroll
        for (int nt = 0; nt < 16; nt++) {
            o[nt][0] *= cr0; o[nt][1] *= cr0;
            o[nt][2] *= cr1; o[nt][3] *= cr1;
        }

        float rs0 = 0.f, rs1 = 0.f;
#pragma unroll
        for (int nt = 0; nt < 8; nt++) {
            float p0 = (s[nt][0] > -1e29f) ? __expf(s[nt][0] - nm0) : 0.f;
            float p1 = (s[nt][1] > -1e29f) ? __expf(s[nt][1] - nm0) : 0.f;
            float p2 = (s[nt][2] > -1e29f) ? __expf(s[nt][2] - nm1) : 0.f;
            float p3 = (s[nt][3] > -1e29f) ? __expf(s[nt][3] - nm1) : 0.f;
            rs0 += p0 + p1; rs1 += p2 + p3;
            int c = nt * 8 + 2 * tg;
            Ps[(m0 + g) * PSTR + c]         = f2tf(p0);
            Ps[(m0 + g) * PSTR + c + 1]     = f2tf(p1);
            Ps[(m0 + 8 + g) * PSTR + c]     = f2tf(p2);
            Ps[(m0 + 8 + g) * PSTR + c + 1] = f2tf(p3);
        }
        rs0 += __shfl_xor_sync(0xffffffffu, rs0, 1);
        rs0 += __shfl_xor_sync(0xffffffffu, rs0, 2);
        rs1 += __shfl_xor_sync(0xffffffffu, rs1, 1);
        rs1 += __shfl_xor_sync(0xffffffffu, rs1, 2);
        li0 = li0 * cr0 + rs0;
        li1 = li1 * cr1 + rs1;
        __syncwarp();   // Ps rows warp-private; order STS -> LDS

        // O += P * V : warp m16 x n128 x k64
#pragma unroll
        for (int kk = 0; kk < 64; kk += 8) {
            uint32_t a[4];
            a[0] = Ps[(m0 + g) * PSTR + kk + tg];
            a[1] = Ps[(m0 + 8 + g) * PSTR + kk + tg];
            a[2] = Ps[(m0 + g) * PSTR + kk + 4 + tg];
            a[3] = Ps[(m0 + 8 + g) * PSTR + kk + 4 + tg];
#pragma unroll
            for (int nt = 0; nt < 16; nt++) {
                uint32_t bf[2];
                bf[0] = Vs[(kk + tg) * VSTR + nt * 8 + g];
                bf[1] = Vs[(kk + 4 + tg) * VSTR + nt * 8 + g];
                mma_tf32(o[nt], a, bf);
            }
        }
        __syncthreads();   // protect Ks/Vs before next tile's load
    }

    // normalize + write
    float inv0 = 1.f / li0, inv1 = 1.f / li1;
#pragma unroll
    for (int nt = 0; nt < 16; nt++) {
        int c = nt * 8 + 2 * tg;
        *(float2*)(&g_o[((size_t)qr0 * NH + head) * HD + c]) =
            make_float2(o[nt][0] * inv0, o[nt][1] * inv0);
        *(float2*)(&g_o[((size_t)qr1 * NH + head) * HD + c]) =
            make_float2(o[nt][2] * inv1, o[nt][3] * inv1);
    }
}

// ---------------- launch -----------------------------------------------------
extern "C" void kernel_launch(void* const* d_in, const int* in_sizes, int n_in,
                              void* d_out, int out_size)
{
    const float* hidden = (const float*)d_in[0];
    const float* cosT   = (const float*)d_in[1];
    const float* sinT   = (const float*)d_in[2];
    const int*   doc    = (const int*)  d_in[3];
    const float* Wq = (const float*)d_in[5];
    const float* bq = (const float*)d_in[6];
    const float* Wk = (const float*)d_in[7];
    const float* bk = (const float*)d_in[8];
    const float* Wv = (const float*)d_in[9];
    const float* bv = (const float*)d_in[10];
    const float* Wo = (const float*)d_in[11];
    float* out = (float*)d_out;

    float *qp, *kp, *vp, *op;
    cudaGetSymbolAddress((void**)&qp, g_q);
    cudaGetSymbolAddress((void**)&kp, g_k);
    cudaGetSymbolAddress((void**)&vp, g_v);
    cudaGetSymbolAddress((void**)&op, g_o);

    // Fused QKV projection (tensor core TF32, cp.async pipelined)
    gemm_qkv<<<dim3(36, SEQ / 128), 256>>>(hidden, Wq, bq, Wk, bk, Wv, bv, qp, kp, vp);

    // Flash attention (RoPE fused into Q/K loads)
    cudaFuncSetAttribute(flash_kernel, cudaFuncAttributeMaxDynamicSharedMemorySize, FLASH_SMEM);
    flash_kernel<<<dim3(SEQ / 128, NH), 256, FLASH_SMEM>>>(doc, cosT, sinT);

    // Output projection
    gemm_out<<<dim3(HID / 128, SEQ / 128), 256>>>(op, Wo, out);
}

// round 4
// speedup vs baseline: 4.1590x; 1.0106x over previous
#include <cuda_runtime.h>
#include <math.h>
#include <stdint.h>

#define SEQ 2048
#define HID 3584
#define NH 28
#define NKV 4
#define GRP 7
#define HD 128
#define SOFT_SCALE 0.08838834764831845f   // 1/sqrt(128)

// ---------------- scratch (static device globals; no runtime allocation) ----
__device__ uint32_t g_hid_t[SEQ * HID];        // hidden as tf32 bits
__device__ uint32_t g_wq_t[NH * HD * HID];
__device__ uint32_t g_wk_t[NKV * HD * HID];
__device__ uint32_t g_wv_t[NKV * HD * HID];
__device__ uint32_t g_wo_t[HID * NH * HD];
__device__ float    g_q[SEQ * NH * HD];        // Q pre-rope (fp32)
__device__ float    g_k[SEQ * NKV * HD];       // K pre-rope (fp32)
__device__ uint32_t g_qt[SEQ * NH * HD];       // rope(Q) tf32
__device__ uint32_t g_kt[SEQ * NKV * HD];      // rope(K) tf32
__device__ uint32_t g_vt[SEQ * NKV * HD];      // V tf32 (from gemm epilogue)
__device__ uint32_t g_ot[SEQ * NH * HD];       // attention out tf32

// ---------------- helpers ----------------------------------------------------
__device__ __forceinline__ uint32_t f2tf(float f) {
    uint32_t u;
    asm("cvt.rna.tf32.f32 %0, %1;" : "=r"(u) : "f"(f));
    return u;
}

__device__ __forceinline__ void mma_tf32(float* c, const uint32_t* a, const uint32_t* b) {
    asm volatile(
        "mma.sync.aligned.m16n8k8.row.col.f32.tf32.tf32.f32 "
        "{%0,%1,%2,%3}, {%4,%5,%6,%7}, {%8,%9}, {%0,%1,%2,%3};"
        : "+f"(c[0]), "+f"(c[1]), "+f"(c[2]), "+f"(c[3])
        : "r"(a[0]), "r"(a[1]), "r"(a[2]), "r"(a[3]), "r"(b[0]), "r"(b[1]));
}

__device__ __forceinline__ uint32_t smem_u32(const void* p) {
    return (uint32_t)__cvta_generic_to_shared(p);
}
__device__ __forceinline__ void cp16(uint32_t s, const void* g) {
    asm volatile("cp.async.cg.shared.global [%0], [%1], 16;" :: "r"(s), "l"(g));
}
#define CP_COMMIT() asm volatile("cp.async.commit_group;" ::: "memory")
#define CP_WAIT(n)  asm volatile("cp.async.wait_group %0;" :: "n"(n) : "memory")

// ---------------- fp32 -> tf32 bulk converter --------------------------------
__global__ void conv_f2t(const float4* __restrict__ src, uint4* __restrict__ dst, int n4)
{
    int i = blockIdx.x * blockDim.x + threadIdx.x;
    if (i < n4) {
        float4 v = src[i];
        dst[i] = make_uint4(f2tf(v.x), f2tf(v.y), f2tf(v.z), f2tf(v.w));
    }
}

// ---------------- rope + tf32 prep for Q/K -----------------------------------
// grid (SEQ, 4), block 128. y handles 7 q-heads + 1 k-head.
__global__ void prep_rope(const float* __restrict__ cosT, const float* __restrict__ sinT)
{
    const int s = blockIdx.x, d = threadIdx.x;
    const float c  = cosT[s * HD + d];
    const float sn = sinT[s * HD + d];
    const float sg = (d < 64) ? -1.f : 1.f;

#pragma unroll
    for (int i = 0; i < 7; i++) {
        int h = blockIdx.y * 7 + i;
        size_t base = ((size_t)s * NH + h) * HD;
        float x  = g_q[base + d];
        float xo = g_q[base + (d ^ 64)];
        g_qt[base + d] = f2tf(fmaf(sg * xo, sn, x * c));
    }
    {
        int h = blockIdx.y;
        size_t base = ((size_t)s * NKV + h) * HD;
        float x  = g_k[base + d];
        float xo = g_k[base + (d ^ 64)];
        g_kt[base + d] = f2tf(fmaf(sg * xo, sn, x * c));
    }
}

// ---------------- TF32 tensor GEMM body: C = A[M,K]*B[N,K]^T + bias ----------
// 128x128 block, 256 threads (8 warps), warp 64x32, BK=16, 3-stage cp.async.
// Operands are pre-converted tf32 bits -> inner loop is pure LDS + MMA.
#define GSTR 20
#define GSTAGE (128 * GSTR)

template <int OUT_TF32>
__device__ __forceinline__ void gemm_body(
    const uint32_t* __restrict__ A, const uint32_t* __restrict__ B,
    const float* __restrict__ bias, void* __restrict__ C,
    int N, int K, int bx, int by, uint32_t* As, uint32_t* Bs)
{
    const int tid  = threadIdx.x;
    const int warp = tid >> 5, lane = tid & 31;
    const int g = lane >> 2, tg = lane & 3;
    const int wm = (warp >> 2) * 64;
    const int wn = (warp & 3) * 32;

    const int row0 = tid >> 2,         kc0 = (tid & 3) * 4;
    const int row1 = (tid + 256) >> 2, kc1 = ((tid + 256) & 3) * 4;

    const uint32_t* Ap0 = A + (size_t)(by * 128 + row0) * K + kc0;
    const uint32_t* Ap1 = A + (size_t)(by * 128 + row1) * K + kc1;
    const uint32_t* Bp0 = B + (size_t)(bx * 128 + row0) * K + kc0;
    const uint32_t* Bp1 = B + (size_t)(bx * 128 + row1) * K + kc1;
    const uint32_t sA0 = smem_u32(As + row0 * GSTR + kc0);
    const uint32_t sA1 = smem_u32(As + row1 * GSTR + kc1);
    const uint32_t sB0 = smem_u32(Bs + row0 * GSTR + kc0);
    const uint32_t sB1 = smem_u32(Bs + row1 * GSTR + kc1);

    float acc[16][4];
#pragma unroll
    for (int i = 0; i < 16; i++)
#pragma unroll
        for (int j = 0; j < 4; j++) acc[i][j] = 0.f;

    const int T = K / 16;
    // prologue: tiles 0 and 1
#pragma unroll
    for (int p = 0; p < 2; p++) {
        const int kb = p * 16;
        const uint32_t so = (uint32_t)(p * GSTAGE * 4);
        cp16(sA0 + so, Ap0 + kb); cp16(sA1 + so, Ap1 + kb);
        cp16(sB0 + so, Bp0 + kb); cp16(sB1 + so, Bp1 + kb);
        CP_COMMIT();
    }

    for (int t = 0; t < T; t++) {
        if (t < T - 1) CP_WAIT(1); else CP_WAIT(0);
        __syncthreads();

        if (t + 2 < T) {
            const int kb = (t + 2) * 16;
            const uint32_t so = (uint32_t)(((t + 2) % 3) * GSTAGE * 4);
            cp16(sA0 + so, Ap0 + kb); cp16(sA1 + so, Ap1 + kb);
            cp16(sB0 + so, Bp0 + kb); cp16(sB1 + so, Bp1 + kb);
            CP_COMMIT();
        }

        const uint32_t* as = As + (t % 3) * GSTAGE;
        const uint32_t* bs = Bs + (t % 3) * GSTAGE;
#pragma unroll
        for (int kk = 0; kk < 16; kk += 8) {
            uint32_t a[4][4], bf[4][2];
#pragma unroll
            for (int mt = 0; mt < 4; mt++) {
                int r = wm + mt * 16;
                a[mt][0] = as[(r + g) * GSTR + kk + tg];
                a[mt][1] = as[(r + 8 + g) * GSTR + kk + tg];
                a[mt][2] = as[(r + g) * GSTR + kk + 4 + tg];
                a[mt][3] = as[(r + 8 + g) * GSTR + kk + 4 + tg];
            }
#pragma unroll
            for (int nt = 0; nt < 4; nt++) {
                int c = wn + nt * 8;
                bf[nt][0] = bs[(c + g) * GSTR + kk + tg];
                bf[nt][1] = bs[(c + g) * GSTR + kk + 4 + tg];
            }
#pragma unroll
            for (int mt = 0; mt < 4; mt++)
#pragma unroll
                for (int nt = 0; nt < 4; nt++)
                    mma_tf32(acc[mt * 4 + nt], a[mt], bf[nt]);
        }
    }
    __syncthreads();

#pragma unroll
    for (int mt = 0; mt < 4; mt++) {
#pragma unroll
        for (int nt = 0; nt < 4; nt++) {
            int r0 = by * 128 + wm + mt * 16 + g;
            int c0 = bx * 128 + wn + nt * 8 + 2 * tg;
            float b0 = bias ? bias[c0] : 0.f;
            float b1 = bias ? bias[c0 + 1] : 0.f;
            float* ca = acc[mt * 4 + nt];
            if (OUT_TF32) {
                uint32_t* Co = (uint32_t*)C;
                *(uint2*)(&Co[(size_t)r0 * N + c0]) =
                    make_uint2(f2tf(ca[0] + b0), f2tf(ca[1] + b1));
                *(uint2*)(&Co[(size_t)(r0 + 8) * N + c0]) =
                    make_uint2(f2tf(ca[2] + b0), f2tf(ca[3] + b1));
            } else {
                float* Co = (float*)C;
                *(float2*)(&Co[(size_t)r0 * N + c0])       = make_float2(ca[0] + b0, ca[1] + b1);
                *(float2*)(&Co[(size_t)(r0 + 8) * N + c0]) = make_float2(ca[2] + b0, ca[3] + b1);
            }
        }
    }
}

// Fused QKV: bx<28 -> Q (fp32 out, rope later), 28..31 -> K (fp32), 32..35 -> V (tf32)
__global__ __launch_bounds__(256) void gemm_qkv(
    const float* __restrict__ bq, const float* __restrict__ bk,
    const float* __restrict__ bv)
{
    __shared__ uint32_t As[3 * GSTAGE];
    __shared__ uint32_t Bs[3 * GSTAGE];
    const int bx = blockIdx.x, by = blockIdx.y;
    if (bx < 28)
        gemm_body<0>(g_hid_t, g_wq_t, bq, g_q, NH * HD, HID, bx, by, As, Bs);
    else if (bx < 32)
        gemm_body<0>(g_hid_t, g_wk_t, bk, g_k, NKV * HD, HID, bx - 28, by, As, Bs);
    else
        gemm_body<1>(g_hid_t, g_wv_t, bv, g_vt, NKV * HD, HID, bx - 32, by, As, Bs);
}

__global__ __launch_bounds__(256) void gemm_out(float* __restrict__ C)
{
    __shared__ uint32_t As[3 * GSTAGE];
    __shared__ uint32_t Bs[3 * GSTAGE];
    gemm_body<0>(g_ot, g_wo_t, nullptr, C, HID, HID, blockIdx.x, blockIdx.y, As, Bs);
}

// ---------------- Flash attention (TF32 mma, fp32 softmax) -------------------
// BQ=128, BKV=64. 256 threads = 8 warps; warp owns 16 full query rows.
// All operands pre-converted tf32 -> tile loads are pure cp.async copies.
#define QSTR 132
#define KSTR 132
#define VSTR 136
#define PSTR 68
#define FLASH_SMEM ((128*QSTR + 64*KSTR + 64*VSTR + 128*PSTR) * 4 + 64 * 4)

__global__ __launch_bounds__(256) void flash_kernel(const int* __restrict__ doc)
{
    extern __shared__ uint32_t fsm[];
    uint32_t* Qs = fsm;                  // [128][QSTR]
    uint32_t* Ks = Qs + 128 * QSTR;      // [64][KSTR]
    uint32_t* Vs = Ks + 64 * KSTR;       // [64][VSTR]
    uint32_t* Ps = Vs + 64 * VSTR;       // [128][PSTR]
    int* kdoc = (int*)(Ps + 128 * PSTR);

    const int qb = gridDim.x - 1 - blockIdx.x;   // longest blocks first
    const int head = blockIdx.y;
    const int kvh = head / GRP;
    const int q0 = qb * 128;
    const int tid = threadIdx.x;
    const int warp = tid >> 5, lane = tid & 31;
    const int g = lane >> 2, tg = lane & 3;
    const int m0 = warp * 16;

    // Q tile: 16 cp16 per thread
    for (int f = tid; f < 128 * 32; f += 256) {
        int row = f >> 5, c4 = (f & 31) * 4;
        cp16(smem_u32(&Qs[row * QSTR + c4]),
             g_qt + ((size_t)(q0 + row) * NH + head) * HD + c4);
    }
    CP_COMMIT();

    const int qr0 = q0 + m0 + g, qr1 = qr0 + 8;
    const int qd0 = doc[qr0], qd1 = doc[qr1];
    float mi0 = -1e30f, mi1 = -1e30f, li0 = 0.f, li1 = 0.f;
    float o[16][4];
#pragma unroll
    for (int i = 0; i < 16; i++)
#pragma unroll
        for (int j = 0; j < 4; j++) o[i][j] = 0.f;

    const int tmax = 2 * qb + 1;
    for (int t = 0; t <= tmax; t++) {
        const int k0 = t * 64;
        for (int f = tid; f < 64 * 32; f += 256) {
            int row = f >> 5, c4 = (f & 31) * 4;
            size_t src = ((size_t)(k0 + row) * NKV + kvh) * HD + c4;
            cp16(smem_u32(&Ks[row * KSTR + c4]), g_kt + src);
            cp16(smem_u32(&Vs[row * VSTR + c4]), g_vt + src);
        }
        CP_COMMIT();
        if (tid < 64) kdoc[tid] = doc[k0 + tid];
        CP_WAIT(0);
        __syncthreads();

        // scores: warp m16 x n64 x k128
        float s[8][4];
#pragma unroll
        for (int i = 0; i < 8; i++)
#pragma unroll
            for (int j = 0; j < 4; j++) s[i][j] = 0.f;

#pragma unroll
        for (int kk = 0; kk < 128; kk += 8) {
            uint32_t a[4];
            a[0] = Qs[(m0 + g) * QSTR + kk + tg];
            a[1] = Qs[(m0 + 8 + g) * QSTR + kk + tg];
            a[2] = Qs[(m0 + g) * QSTR + kk + 4 + tg];
            a[3] = Qs[(m0 + 8 + g) * QSTR + kk + 4 + tg];
#pragma unroll
            for (int nt = 0; nt < 8; nt++) {
                uint32_t bf[2];
                bf[0] = Ks[(nt * 8 + g) * KSTR + kk + tg];
                bf[1] = Ks[(nt * 8 + g) * KSTR + kk + 4 + tg];
                mma_tf32(s[nt], a, bf);
            }
        }

        // mask + scale
        float mx0 = -1e30f, mx1 = -1e30f;
#pragma unroll
        for (int nt = 0; nt < 8; nt++) {
            int c0 = k0 + nt * 8 + 2 * tg;
            int d0 = kdoc[nt * 8 + 2 * tg];
            int d1 = kdoc[nt * 8 + 2 * tg + 1];
            s[nt][0] = (qr0 >= c0     && qd0 == d0) ? s[nt][0] * SOFT_SCALE : -1e30f;
            s[nt][1] = (qr0 >= c0 + 1 && qd0 == d1) ? s[nt][1] * SOFT_SCALE : -1e30f;
            s[nt][2] = (qr1 >= c0     && qd1 == d0) ? s[nt][2] * SOFT_SCALE : -1e30f;
            s[nt][3] = (qr1 >= c0 + 1 && qd1 == d1) ? s[nt][3] * SOFT_SCALE : -1e30f;
            mx0 = fmaxf(mx0, fmaxf(s[nt][0], s[nt][1]));
            mx1 = fmaxf(mx1, fmaxf(s[nt][2], s[nt][3]));
        }
        mx0 = fmaxf(mx0, __shfl_xor_sync(0xffffffffu, mx0, 1));
        mx0 = fmaxf(mx0, __shfl_xor_sync(0xffffffffu, mx0, 2));
        mx1 = fmaxf(mx1, __shfl_xor_sync(0xffffffffu, mx1, 1));
        mx1 = fmaxf(mx1, __shfl_xor_sync(0xffffffffu, mx1, 2));

        float nm0 = fmaxf(mi0, mx0), nm1 = fmaxf(mi1, mx1);
        float cr0 = __expf(mi0 - nm0), cr1 = __expf(mi1 - nm1);
        mi0 = nm0; mi1 = nm1;
#pragma unroll
        for (int nt = 0; nt < 16; nt++) {
            o[nt][0] *= cr0; o[nt][1] *= cr0;
            o[nt][2] *= cr1; o[nt][3] *= cr1;
        }

        float rs0 = 0.f, rs1 = 0.f;
#pragma unroll
        for (int nt = 0; nt < 8; nt++) {
            float p0 = (s[nt][0] > -1e29f) ? __expf(s[nt][0] - nm0) : 0.f;
            float p1 = (s[nt][1] > -1e29f) ? __expf(s[nt][1] - nm0) : 0.f;
            float p2 = (s[nt][2] > -1e29f) ? __expf(s[nt][2] - nm1) : 0.f;
            float p3 = (s[nt][3] > -1e29f) ? __expf(s[nt][3] - nm1) : 0.f;
            rs0 += p0 + p1; rs1 += p2 + p3;
            int c = nt * 8 + 2 * tg;
            Ps[(m0 + g) * PSTR + c]         = f2tf(p0);
            Ps[(m0 + g) * PSTR + c + 1]     = f2tf(p1);
            Ps[(m0 + 8 + g) * PSTR + c]     = f2tf(p2);
            Ps[(m0 + 8 + g) * PSTR + c + 1] = f2tf(p3);
        }
        rs0 += __shfl_xor_sync(0xffffffffu, rs0, 1);
        rs0 += __shfl_xor_sync(0xffffffffu, rs0, 2);
        rs1 += __shfl_xor_sync(0xffffffffu, rs1, 1);
        rs1 += __shfl_xor_sync(0xffffffffu, rs1, 2);
        li0 = li0 * cr0 + rs0;
        li1 = li1 * cr1 + rs1;
        __syncwarp();   // Ps rows warp-private; STS -> LDS order

        // O += P * V : warp m16 x n128 x k64
#pragma unroll
        for (int kk = 0; kk < 64; kk += 8) {
            uint32_t a[4];
            a[0] = Ps[(m0 + g) * PSTR + kk + tg];
            a[1] = Ps[(m0 + 8 + g) * PSTR + kk + tg];
            a[2] = Ps[(m0 + g) * PSTR + kk + 4 + tg];
            a[3] = Ps[(m0 + 8 + g) * PSTR + kk + 4 + tg];
#pragma unroll
            for (int nt = 0; nt < 16; nt++) {
                uint32_t bf[2];
                bf[0] = Vs[(kk + tg) * VSTR + nt * 8 + g];
                bf[1] = Vs[(kk + 4 + tg) * VSTR + nt * 8 + g];
                mma_tf32(o[nt], a, bf);
            }
        }
        __syncthreads();   // protect Ks/Vs before next tile's cp.async
    }

    // normalize + write as tf32 (A operand of the O projection)
    float inv0 = 1.f / li0, inv1 = 1.f / li1;
#pragma unroll
    for (int nt = 0; nt < 16; nt++) {
        int c = nt * 8 + 2 * tg;
        *(uint2*)(&g_ot[((size_t)qr0 * NH + head) * HD + c]) =
            make_uint2(f2tf(o[nt][0] * inv0), f2tf(o[nt][1] * inv0));
        *(uint2*)(&g_ot[((size_t)qr1 * NH + head) * HD + c]) =
            make_uint2(f2tf(o[nt][2] * inv1), f2tf(o[nt][3] * inv1));
    }
}

// ---------------- launch -----------------------------------------------------
extern "C" void kernel_launch(void* const* d_in, const int* in_sizes, int n_in,
                              void* d_out, int out_size)
{
    const float* hidden = (const float*)d_in[0];
    const float* cosT   = (const float*)d_in[1];
    const float* sinT   = (const float*)d_in[2];
    const int*   doc    = (const int*)  d_in[3];
    const float* Wq = (const float*)d_in[5];
    const float* bq = (const float*)d_in[6];
    const float* Wk = (const float*)d_in[7];
    const float* bk = (const float*)d_in[8];
    const float* Wv = (const float*)d_in[9];
    const float* bv = (const float*)d_in[10];
    const float* Wo = (const float*)d_in[11];
    float* out = (float*)d_out;

    void *hid_t, *wq_t, *wk_t, *wv_t, *wo_t;
    cudaGetSymbolAddress(&hid_t, g_hid_t);
    cudaGetSymbolAddress(&wq_t, g_wq_t);
    cudaGetSymbolAddress(&wk_t, g_wk_t);
    cudaGetSymbolAddress(&wv_t, g_wv_t);
    cudaGetSymbolAddress(&wo_t, g_wo_t);

    // 1) bulk fp32 -> tf32 conversion of hidden + weights
    {
        struct { const void* s; void* d; int n; } cv[5] = {
            {hidden, hid_t, SEQ * HID},
            {Wq, wq_t, NH * HD * HID},
            {Wk, wk_t, NKV * HD * HID},
            {Wv, wv_t, NKV * HD * HID},
            {Wo, wo_t, HID * NH * HD},
        };
        for (int i = 0; i < 5; i++) {
            int n4 = cv[i].n / 4;
            conv_f2t<<<(n4 + 255) / 256, 256>>>((const float4*)cv[i].s, (uint4*)cv[i].d, n4);
        }
    }

    // 2) QKV projections (pure tensor GEMM; V epilogue emits tf32)
    gemm_qkv<<<dim3(36, SEQ / 128), 256>>>(bq, bk, bv);

    // 3) RoPE + tf32 for Q/K
    prep_rope<<<dim3(SEQ, 4), HD>>>(cosT, sinT);

    // 4) Flash attention (pure copies + mma); writes tf32 attention output
    cudaFuncSetAttribute(flash_kernel, cudaFuncAttributeMaxDynamicSharedMemorySize, FLASH_SMEM);
    flash_kernel<<<dim3(SEQ / 128, NH), 256, FLASH_SMEM>>>(doc);

    // 5) Output projection
    gemm_out<<<dim3(HID / 128, SEQ / 128), 256>>>(out);
}

// round 5
// speedup vs baseline: 4.3989x; 1.0577x over previous
#include <cuda_runtime.h>
#include <math.h>
#include <stdint.h>

#define SEQ 2048
#define HID 3584
#define NH 28
#define NKV 4
#define GRP 7
#define HD 128
#define SOFT_SCALE 0.08838834764831845f   // 1/sqrt(128)

// ---------------- scratch (static device globals; no runtime allocation) ----
// *_t arrays are tf32 bits, K-dim-permuted: within each 8-group, storage
// position p holds true k = (p&~7) | ((p>>1)&3) | ((p&1)<<2).
__device__ uint32_t g_hid_t[SEQ * HID];
__device__ uint32_t g_wq_t[NH * HD * HID];
__device__ uint32_t g_wk_t[NKV * HD * HID];
__device__ uint32_t g_wv_t[NKV * HD * HID];
__device__ uint32_t g_wo_t[HID * NH * HD];
__device__ float    g_q[SEQ * NH * HD];        // Q pre-rope fp32
__device__ float    g_k[SEQ * NKV * HD];       // K pre-rope fp32
__device__ uint32_t g_qt[SEQ * NH * HD];       // rope(Q) tf32, d-permuted
__device__ uint32_t g_kt[SEQ * NKV * HD];      // rope(K) tf32, d-permuted
__device__ uint32_t g_vt[SEQ * NKV * HD];      // V tf32 (true layout)
__device__ uint32_t g_ot[SEQ * NH * HD];       // attn out tf32, d-permuted

// ---------------- helpers ----------------------------------------------------
__device__ __forceinline__ uint32_t f2tf(float f) {
    uint32_t u;
    asm("cvt.rna.tf32.f32 %0, %1;" : "=r"(u) : "f"(f));
    return u;
}
__device__ __forceinline__ void mma_tf32(float* c, const uint32_t* a, const uint32_t* b) {
    asm volatile(
        "mma.sync.aligned.m16n8k8.row.col.f32.tf32.tf32.f32 "
        "{%0,%1,%2,%3}, {%4,%5,%6,%7}, {%8,%9}, {%0,%1,%2,%3};"
        : "+f"(c[0]), "+f"(c[1]), "+f"(c[2]), "+f"(c[3])
        : "r"(a[0]), "r"(a[1]), "r"(a[2]), "r"(a[3]), "r"(b[0]), "r"(b[1]));
}
__device__ __forceinline__ uint32_t smem_u32(const void* p) {
    return (uint32_t)__cvta_generic_to_shared(p);
}
__device__ __forceinline__ void cp16(uint32_t s, const void* g) {
    asm volatile("cp.async.cg.shared.global [%0], [%1], 16;" :: "r"(s), "l"(g));
}
#define CP_COMMIT() asm volatile("cp.async.commit_group;" ::: "memory")
#define CP_WAIT(n)  asm volatile("cp.async.wait_group %0;" :: "n"(n) : "memory")

// ---------------- fp32 -> tf32 converter with K-permutation ------------------
__global__ void conv_perm(const float* __restrict__ src, uint32_t* __restrict__ dst, int n)
{
    int i = (blockIdx.x * blockDim.x + threadIdx.x) * 4;
    if (i < n) {
        uint4 r;
        uint32_t* rp = (uint32_t*)&r;
#pragma unroll
        for (int j = 0; j < 4; j++) {
            int p = i + j;
            int k = (p & ~7) | ((p >> 1) & 3) | ((p & 1) << 2);
            rp[j] = f2tf(src[k]);
        }
        *(uint4*)(dst + i) = r;
    }
}

// ---------------- rope + tf32 + permute for Q/K ------------------------------
__global__ void prep_rope(const float* __restrict__ cosT, const float* __restrict__ sinT)
{
    const int s = blockIdx.x, d = threadIdx.x;
    const float c  = cosT[s * HD + d];
    const float sn = sinT[s * HD + d];
    const float sg = (d < 64) ? -1.f : 1.f;
    const int dp = (d & ~7) | ((d & 3) << 1) | ((d >> 2) & 1);   // permuted pos

#pragma unroll
    for (int i = 0; i < 7; i++) {
        int h = blockIdx.y * 7 + i;
        size_t base = ((size_t)s * NH + h) * HD;
        float x  = g_q[base + d];
        float xo = g_q[base + (d ^ 64)];
        g_qt[base + dp] = f2tf(fmaf(sg * xo, sn, x * c));
    }
    {
        size_t base = ((size_t)s * NKV + blockIdx.y) * HD;
        float x  = g_k[base + d];
        float xo = g_k[base + (d ^ 64)];
        g_kt[base + dp] = f2tf(fmaf(sg * xo, sn, x * c));
    }
}

// ---------------- TF32 tensor GEMM body: C = A[M,K]*B[N,K]^T + bias ----------
// 128x128 block, 256 threads (8 warps), warp 64x32, BK=16, 3-stage cp.async.
// A,B pre-permuted -> all fragment loads are LDS.64.
#define GSTR 24
#define GSTAGE (128 * GSTR)
#define GEMM_SMEM (3 * GSTAGE * 2 * 4)

template <int OUT_TF32>
__device__ __forceinline__ void gemm_body(
    const uint32_t* __restrict__ A, const uint32_t* __restrict__ B,
    const float* __restrict__ bias, void* __restrict__ C,
    int N, int K, int bx, int by, uint32_t* As, uint32_t* Bs)
{
    const int tid  = threadIdx.x;
    const int warp = tid >> 5, lane = tid & 31;
    const int g = lane >> 2, tg = lane & 3;
    const int wm = (warp >> 2) * 64;
    const int wn = (warp & 3) * 32;

    const int row0 = tid >> 2,         kc0 = (tid & 3) * 4;
    const int row1 = (tid + 256) >> 2, kc1 = ((tid + 256) & 3) * 4;

    const uint32_t* Ap0 = A + (size_t)(by * 128 + row0) * K + kc0;
    const uint32_t* Ap1 = A + (size_t)(by * 128 + row1) * K + kc1;
    const uint32_t* Bp0 = B + (size_t)(bx * 128 + row0) * K + kc0;
    const uint32_t* Bp1 = B + (size_t)(bx * 128 + row1) * K + kc1;
    const uint32_t sA0 = smem_u32(As + row0 * GSTR + kc0);
    const uint32_t sA1 = smem_u32(As + row1 * GSTR + kc1);
    const uint32_t sB0 = smem_u32(Bs + row0 * GSTR + kc0);
    const uint32_t sB1 = smem_u32(Bs + row1 * GSTR + kc1);

    float acc[16][4];
#pragma unroll
    for (int i = 0; i < 16; i++)
#pragma unroll
        for (int j = 0; j < 4; j++) acc[i][j] = 0.f;

    const int T = K / 16;
#pragma unroll
    for (int p = 0; p < 2; p++) {
        const int kb = p * 16;
        const uint32_t so = (uint32_t)(p * GSTAGE * 4);
        cp16(sA0 + so, Ap0 + kb); cp16(sA1 + so, Ap1 + kb);
        cp16(sB0 + so, Bp0 + kb); cp16(sB1 + so, Bp1 + kb);
        CP_COMMIT();
    }

    for (int t = 0; t < T; t++) {
        if (t < T - 1) CP_WAIT(1); else CP_WAIT(0);
        __syncthreads();

        if (t + 2 < T) {
            const int kb = (t + 2) * 16;
            const uint32_t so = (uint32_t)(((t + 2) % 3) * GSTAGE * 4);
            cp16(sA0 + so, Ap0 + kb); cp16(sA1 + so, Ap1 + kb);
            cp16(sB0 + so, Bp0 + kb); cp16(sB1 + so, Bp1 + kb);
            CP_COMMIT();
        }

        const uint32_t* as = As + (t % 3) * GSTAGE;
        const uint32_t* bs = Bs + (t % 3) * GSTAGE;
#pragma unroll
        for (int kk = 0; kk < 16; kk += 8) {
            uint32_t a[4][4], bf[4][2];
#pragma unroll
            for (int mt = 0; mt < 4; mt++) {
                int r = wm + mt * 16;
                uint2 x = *(const uint2*)&as[(r + g) * GSTR + kk + 2 * tg];
                uint2 y = *(const uint2*)&as[(r + 8 + g) * GSTR + kk + 2 * tg];
                a[mt][0] = x.x; a[mt][1] = y.x; a[mt][2] = x.y; a[mt][3] = y.y;
            }
#pragma unroll
            for (int nt = 0; nt < 4; nt++) {
                uint2 u = *(const uint2*)&bs[(wn + nt * 8 + g) * GSTR + kk + 2 * tg];
                bf[nt][0] = u.x; bf[nt][1] = u.y;
            }
#pragma unroll
            for (int mt = 0; mt < 4; mt++)
#pragma unroll
                for (int nt = 0; nt < 4; nt++)
                    mma_tf32(acc[mt * 4 + nt], a[mt], bf[nt]);
        }
    }
    __syncthreads();

#pragma unroll
    for (int mt = 0; mt < 4; mt++) {
#pragma unroll
        for (int nt = 0; nt < 4; nt++) {
            int r0 = by * 128 + wm + mt * 16 + g;
            int c0 = bx * 128 + wn + nt * 8 + 2 * tg;
            float b0 = bias ? bias[c0] : 0.f;
            float b1 = bias ? bias[c0 + 1] : 0.f;
            float* ca = acc[mt * 4 + nt];
            if (OUT_TF32) {
                uint32_t* Co = (uint32_t*)C;
                *(uint2*)(&Co[(size_t)r0 * N + c0]) =
                    make_uint2(f2tf(ca[0] + b0), f2tf(ca[1] + b1));
                *(uint2*)(&Co[(size_t)(r0 + 8) * N + c0]) =
                    make_uint2(f2tf(ca[2] + b0), f2tf(ca[3] + b1));
            } else {
                float* Co = (float*)C;
                *(float2*)(&Co[(size_t)r0 * N + c0])       = make_float2(ca[0] + b0, ca[1] + b1);
                *(float2*)(&Co[(size_t)(r0 + 8) * N + c0]) = make_float2(ca[2] + b0, ca[3] + b1);
            }
        }
    }
}

__global__ __launch_bounds__(256) void gemm_qkv(
    const float* __restrict__ bq, const float* __restrict__ bk,
    const float* __restrict__ bv)
{
    extern __shared__ uint32_t gsm[];
    uint32_t* As = gsm;
    uint32_t* Bs = gsm + 3 * GSTAGE;
    const int bx = blockIdx.x, by = blockIdx.y;
    if (bx < 28)
        gemm_body<0>(g_hid_t, g_wq_t, bq, g_q, NH * HD, HID, bx, by, As, Bs);
    else if (bx < 32)
        gemm_body<0>(g_hid_t, g_wk_t, bk, g_k, NKV * HD, HID, bx - 28, by, As, Bs);
    else
        gemm_body<1>(g_hid_t, g_wv_t, bv, g_vt, NKV * HD, HID, bx - 32, by, As, Bs);
}

__global__ __launch_bounds__(256) void gemm_out(float* __restrict__ C)
{
    extern __shared__ uint32_t gsm[];
    gemm_body<0>(g_ot, g_wo_t, nullptr, C, HID, HID, blockIdx.x, blockIdx.y,
                 gsm, gsm + 3 * GSTAGE);
}

// ---------------- Flash attention (TF32 mma, fp32 softmax, pipelined) --------
// BQ=128, BKV=64. 8 warps, warp owns 16 query rows. K double-buffered,
// V single-buffered (issued post-PV, waited pre-PV next tile).
#define QSTR 136
#define KSTR 136
#define VSTR 136
#define PSTR 72
#define KVTILE (64 * KSTR)
#define FLASH_SMEM ((128*QSTR + 2*KVTILE + 64*VSTR + 128*PSTR) * 4 + 64 * 4)

__global__ __launch_bounds__(256) void flash_kernel(const int* __restrict__ doc)
{
    extern __shared__ uint32_t fsm[];
    uint32_t* Qs = fsm;                      // [128][QSTR] permuted d
    uint32_t* Ks = Qs + 128 * QSTR;          // 2 x [64][KSTR] permuted d
    uint32_t* Vs = Ks + 2 * KVTILE;          // [64][VSTR] true layout
    uint32_t* Ps = Vs + 64 * VSTR;           // [128][PSTR] permuted k
    int* kdoc = (int*)(Ps + 128 * PSTR);

    const int qb = gridDim.x - 1 - blockIdx.x;
    const int head = blockIdx.y;
    const int kvh = head / GRP;
    const int q0 = qb * 128;
    const int tid = threadIdx.x;
    const int warp = tid >> 5, lane = tid & 31;
    const int g = lane >> 2, tg = lane & 3;
    const int m0 = warp * 16;
    // permuted low-3 positions for columns 2tg, 2tg+1
    const int p0 = (((2 * tg) & 3) << 1) | ((2 * tg) >> 2);
    const int p1 = (((2 * tg + 1) & 3) << 1) | ((2 * tg + 1) >> 2);

    // prologue: Q group, K0 group, V0 group
    for (int f = tid; f < 128 * 32; f += 256) {
        int row = f >> 5, c4 = (f & 31) * 4;
        cp16(smem_u32(&Qs[row * QSTR + c4]),
             g_qt + ((size_t)(q0 + row) * NH + head) * HD + c4);
    }
    CP_COMMIT();
    for (int f = tid; f < 64 * 32; f += 256) {
        int row = f >> 5, c4 = (f & 31) * 4;
        cp16(smem_u32(&Ks[row * KSTR + c4]),
             g_kt + ((size_t)row * NKV + kvh) * HD + c4);
    }
    CP_COMMIT();
    for (int f = tid; f < 64 * 32; f += 256) {
        int row = f >> 5, c4 = (f & 31) * 4;
        cp16(smem_u32(&Vs[row * VSTR + c4]),
             g_vt + ((size_t)row * NKV + kvh) * HD + c4);
    }
    CP_COMMIT();

    const int qr0 = q0 + m0 + g, qr1 = qr0 + 8;
    const int qd0 = doc[qr0], qd1 = doc[qr1];
    float mi0 = -1e30f, mi1 = -1e30f, li0 = 0.f, li1 = 0.f;
    float o[16][4];
#pragma unroll
    for (int i = 0; i < 16; i++)
#pragma unroll
        for (int j = 0; j < 4; j++) o[i][j] = 0.f;

    const int tmax = 2 * qb + 1;
    for (int t = 0; t <= tmax; t++) {
        const int k0 = t * 64;
        if (tid < 64) kdoc[tid] = doc[k0 + tid];
        CP_WAIT(1);                 // own K_t parts done (V_t may pend)
        __syncthreads();            // K_t + kdoc visible; prior PV done

        const uint32_t* ks = Ks + (t & 1) * KVTILE;

        // scores: warp m16 x n64 x k128 (all frag loads LDS.64)
        float s[8][4];
#pragma unroll
        for (int i = 0; i < 8; i++)
#pragma unroll
            for (int j = 0; j < 4; j++) s[i][j] = 0.f;

#pragma unroll
        for (int kk = 0; kk < 128; kk += 8) {
            uint32_t a[4];
            uint2 x = *(const uint2*)&Qs[(m0 + g) * QSTR + kk + 2 * tg];
            uint2 y = *(const uint2*)&Qs[(m0 + 8 + g) * QSTR + kk + 2 * tg];
            a[0] = x.x; a[1] = y.x; a[2] = x.y; a[3] = y.y;
#pragma unroll
            for (int nt = 0; nt < 8; nt++) {
                uint2 u = *(const uint2*)&ks[(nt * 8 + g) * KSTR + kk + 2 * tg];
                uint32_t bf[2] = {u.x, u.y};
                mma_tf32(s[nt], a, bf);
            }
        }

        // mask + scale + row max
        float mx0 = -1e30f, mx1 = -1e30f;
#pragma unroll
        for (int nt = 0; nt < 8; nt++) {
            int c0 = k0 + nt * 8 + 2 * tg;
            int d0 = kdoc[nt * 8 + 2 * tg];
            int d1 = kdoc[nt * 8 + 2 * tg + 1];
            s[nt][0] = (qr0 >= c0     && qd0 == d0) ? s[nt][0] * SOFT_SCALE : -1e30f;
            s[nt][1] = (qr0 >= c0 + 1 && qd0 == d1) ? s[nt][1] * SOFT_SCALE : -1e30f;
            s[nt][2] = (qr1 >= c0     && qd1 == d0) ? s[nt][2] * SOFT_SCALE : -1e30f;
            s[nt][3] = (qr1 >= c0 + 1 && qd1 == d1) ? s[nt][3] * SOFT_SCALE : -1e30f;
            mx0 = fmaxf(mx0, fmaxf(s[nt][0], s[nt][1]));
            mx1 = fmaxf(mx1, fmaxf(s[nt][2], s[nt][3]));
        }
        mx0 = fmaxf(mx0, __shfl_xor_sync(0xffffffffu, mx0, 1));
        mx0 = fmaxf(mx0, __shfl_xor_sync(0xffffffffu, mx0, 2));
        mx1 = fmaxf(mx1, __shfl_xor_sync(0xffffffffu, mx1, 1));
        mx1 = fmaxf(mx1, __shfl_xor_sync(0xffffffffu, mx1, 2));

        float nm0 = fmaxf(mi0, mx0), nm1 = fmaxf(mi1, mx1);
        float cr0 = __expf(mi0 - nm0), cr1 = __expf(mi1 - nm1);
        mi0 = nm0; mi1 = nm1;
#pragma unroll
        for (int nt = 0; nt < 16; nt++) {
            o[nt][0] *= cr0; o[nt][1] *= cr0;
            o[nt][2] *= cr1; o[nt][3] *= cr1;
        }

        float rs0 = 0.f, rs1 = 0.f;
#pragma unroll
        for (int nt = 0; nt < 8; nt++) {
            float pe0 = (s[nt][0] > -1e29f) ? __expf(s[nt][0] - nm0) : 0.f;
            float pe1 = (s[nt][1] > -1e29f) ? __expf(s[nt][1] - nm0) : 0.f;
            float pe2 = (s[nt][2] > -1e29f) ? __expf(s[nt][2] - nm1) : 0.f;
            float pe3 = (s[nt][3] > -1e29f) ? __expf(s[nt][3] - nm1) : 0.f;
            rs0 += pe0 + pe1; rs1 += pe2 + pe3;
            int cb = nt * 8;
            Ps[(m0 + g) * PSTR + cb + p0]     = f2tf(pe0);
            Ps[(m0 + g) * PSTR + cb + p1]     = f2tf(pe1);
            Ps[(m0 + 8 + g) * PSTR + cb + p0] = f2tf(pe2);
            Ps[(m0 + 8 + g) * PSTR + cb + p1] = f2tf(pe3);
        }
        rs0 += __shfl_xor_sync(0xffffffffu, rs0, 1);
        rs0 += __shfl_xor_sync(0xffffffffu, rs0, 2);
        rs1 += __shfl_xor_sync(0xffffffffu, rs1, 1);
        rs1 += __shfl_xor_sync(0xffffffffu, rs1, 2);
        li0 = li0 * cr0 + rs0;
        li1 = li1 * cr1 + rs1;

        // prefetch K_{t+1} into other stage; then wait own V_t
        if (t < tmax) {
            const int kn = k0 + 64;
            uint32_t* kd = Ks + ((t + 1) & 1) * KVTILE;
            for (int f = tid; f < 64 * 32; f += 256) {
                int row = f >> 5, c4 = (f & 31) * 4;
                cp16(smem_u32(&kd[row * KSTR + c4]),
                     g_kt + ((size_t)(kn + row) * NKV + kvh) * HD + c4);
            }
            CP_COMMIT();
            CP_WAIT(1);             // V_t done (K_{t+1} pending)
        } else {
            CP_WAIT(0);
        }
        __syncthreads();            // V_t visible to all (also orders Ps)

        // O += P * V : warp m16 x n128 x k64
#pragma unroll
        for (int kk = 0; kk < 64; kk += 8) {
            uint32_t a[4];
            uint2 x = *(const uint2*)&Ps[(m0 + g) * PSTR + kk + 2 * tg];
            uint2 y = *(const uint2*)&Ps[(m0 + 8 + g) * PSTR + kk + 2 * tg];
            a[0] = x.x; a[1] = y.x; a[2] = x.y; a[3] = y.y;
#pragma unroll
            for (int nt = 0; nt < 16; nt++) {
                uint32_t bf[2];
                bf[0] = Vs[(kk + tg) * VSTR + nt * 8 + g];
                bf[1] = Vs[(kk + 4 + tg) * VSTR + nt * 8 + g];
                mma_tf32(o[nt], a, bf);
            }
        }
        __syncthreads();            // PV done everywhere

        // issue V_{t+1} into Vs (overwrites V_t, now safe)
        if (t < tmax) {
            const int kn = k0 + 64;
            for (int f = tid; f < 64 * 32; f += 256) {
                int row = f >> 5, c4 = (f & 31) * 4;
                cp16(smem_u32(&Vs[row * VSTR + c4]),
                     g_vt + ((size_t)(kn + row) * NKV + kvh) * HD + c4);
            }
            CP_COMMIT();
        }
    }

    // normalize + write permuted tf32 (A operand of O projection)
    float inv0 = 1.f / li0, inv1 = 1.f / li1;
#pragma unroll
    for (int nt = 0; nt < 16; nt++) {
        int cb = nt * 8;
        size_t b0 = ((size_t)qr0 * NH + head) * HD + cb;
        size_t b1 = ((size_t)qr1 * NH + head) * HD + cb;
        g_ot[b0 + p0] = f2tf(o[nt][0] * inv0);
        g_ot[b0 + p1] = f2tf(o[nt][1] * inv0);
        g_ot[b1 + p0] = f2tf(o[nt][2] * inv1);
        g_ot[b1 + p1] = f2tf(o[nt][3] * inv1);
    }
}

// ---------------- launch -----------------------------------------------------
extern "C" void kernel_launch(void* const* d_in, const int* in_sizes, int n_in,
                              void* d_out, int out_size)
{
    const float* hidden = (const float*)d_in[0];
    const float* cosT   = (const float*)d_in[1];
    const float* sinT   = (const float*)d_in[2];
    const int*   doc    = (const int*)  d_in[3];
    const float* Wq = (const float*)d_in[5];
    const float* bq = (const float*)d_in[6];
    const float* Wk = (const float*)d_in[7];
    const float* bk = (const float*)d_in[8];
    const float* Wv = (const float*)d_in[9];
    const float* bv = (const float*)d_in[10];
    const float* Wo = (const float*)d_in[11];
    float* out = (float*)d_out;

    void *hid_t, *wq_t, *wk_t, *wv_t, *wo_t;
    cudaGetSymbolAddress(&hid_t, g_hid_t);
    cudaGetSymbolAddress(&wq_t, g_wq_t);
    cudaGetSymbolAddress(&wk_t, g_wk_t);
    cudaGetSymbolAddress(&wv_t, g_wv_t);
    cudaGetSymbolAddress(&wo_t, g_wo_t);

    // 1) fp32 -> tf32 + K-permute for hidden + all weights
    {
        struct { const void* s; void* d; int n; } cv[5] = {
            {hidden, hid_t, SEQ * HID},
            {Wq, wq_t, NH * HD * HID},
            {Wk, wk_t, NKV * HD * HID},
            {Wv, wv_t, NKV * HD * HID},
            {Wo, wo_t, HID * NH * HD},
        };
        for (int i = 0; i < 5; i++) {
            int n4 = cv[i].n / 4;
            conv_perm<<<(n4 + 255) / 256, 256>>>((const float*)cv[i].s,
                                                 (uint32_t*)cv[i].d, cv[i].n);
        }
    }

    // 2) fused QKV projections
    cudaFuncSetAttribute(gemm_qkv, cudaFuncAttributeMaxDynamicSharedMemorySize, GEMM_SMEM);
    gemm_qkv<<<dim3(36, SEQ / 128), 256, GEMM_SMEM>>>(bq, bk, bv);

    // 3) RoPE + tf32 + permute for Q/K
    prep_rope<<<dim3(SEQ, 4), HD>>>(cosT, sinT);

    // 4) flash attention
    cudaFuncSetAttribute(flash_kernel, cudaFuncAttributeMaxDynamicSharedMemorySize, FLASH_SMEM);
    flash_kernel<<<dim3(SEQ / 128, NH), 256, FLASH_SMEM>>>(doc);

    // 5) output projection
    cudaFuncSetAttribute(gemm_out, cudaFuncAttributeMaxDynamicSharedMemorySize, GEMM_SMEM);
    gemm_out<<<dim3(HID / 128, SEQ / 128), 256, GEMM_SMEM>>>(out);
}

// round 10
// speedup vs baseline: 7.1742x; 1.6309x over previous
#include <cuda_runtime.h>
#include <cuda_fp16.h>
#include <math.h>
#include <stdint.h>

#define SEQ 2048
#define HID 3584
#define NH 28
#define NKV 4
#define GRP 7
#define HD 128
#define SOFT_SCALE 0.08838834764831845f   // 1/sqrt(128)

// ---------------- scratch (static device globals; no runtime allocation) ----
// __half arrays are pair-interleave permuted along K: within each 16-group,
// storage pair position sp of true pair p is sp = ((p&3)<<1)|(p>>2).
__device__ __half g_hid_t[SEQ * HID];
__device__ __half g_wq_t[NH * HD * HID];
__device__ __half g_wk_t[NKV * HD * HID];
__device__ __half g_wv_t[NKV * HD * HID];
__device__ __half g_wo_t[HID * NH * HD];
__device__ float  g_q[SEQ * NH * HD];        // Q pre-rope fp32
__device__ float  g_k[SEQ * NKV * HD];       // K pre-rope fp32
__device__ __half g_qt[SEQ * NH * HD];       // rope(Q) fp16, d-permuted
__device__ __half g_kt[SEQ * NKV * HD];      // rope(K) fp16, d-permuted
__device__ __half g_vtT[NKV * HD * SEQ];     // V fp16 TRANSPOSED [h*d][s'], s-permuted
__device__ __half g_ot[SEQ * NH * HD];       // attn out fp16, k-permuted

// ---------------- helpers ----------------------------------------------------
__device__ __forceinline__ int perm16(int k) {       // true k -> storage pos
    int p = (k >> 1) & 7;
    return (k & ~15) | ((((p & 3) << 1) | (p >> 2)) << 1) | (k & 1);
}
__device__ __forceinline__ void mma_f16(float* c, const uint32_t* a, const uint32_t* b) {
    asm volatile(
        "mma.sync.aligned.m16n8k16.row.col.f32.f16.f16.f32 "
        "{%0,%1,%2,%3}, {%4,%5,%6,%7}, {%8,%9}, {%0,%1,%2,%3};"
        : "+f"(c[0]), "+f"(c[1]), "+f"(c[2]), "+f"(c[3])
        : "r"(a[0]), "r"(a[1]), "r"(a[2]), "r"(a[3]), "r"(b[0]), "r"(b[1]));
}
__device__ __forceinline__ uint32_t smem_u32(const void* p) {
    return (uint32_t)__cvta_generic_to_shared(p);
}
__device__ __forceinline__ void cp16(uint32_t s, const void* g) {
    asm volatile("cp.async.cg.shared.global [%0], [%1], 16;" :: "r"(s), "l"(g));
}
#define CP_COMMIT() asm volatile("cp.async.commit_group;" ::: "memory")
#define CP_WAIT(n)  asm volatile("cp.async.wait_group %0;" :: "n"(n) : "memory")

// ---------------- fp32 -> fp16 converter with pair-interleave ---------------
__global__ void conv_h(const float* __restrict__ src, __half* __restrict__ dst, int n)
{
    int base = (blockIdx.x * blockDim.x + threadIdx.x) * 8;
    if (base < n) {
        __half h[8];
#pragma unroll
        for (int j = 0; j < 8; j++) {
            int sidx = base + j;
            int spr = (sidx >> 1) & 7;
            int p = (spr >> 1) | ((spr & 1) << 2);
            int k = (sidx & ~15) | (p << 1) | (sidx & 1);
            h[j] = __float2half_rn(src[k]);
        }
        *(uint4*)(dst + base) = *(uint4*)h;
    }
}

// ---------------- rope + fp16 + permute for Q/K ------------------------------
__global__ void prep_rope(const float* __restrict__ cosT, const float* __restrict__ sinT)
{
    const int s = blockIdx.x, d = threadIdx.x;
    const float c  = cosT[s * HD + d];
    const float sn = sinT[s * HD + d];
    const float sg = (d < 64) ? -1.f : 1.f;
    const int dp = perm16(d);

#pragma unroll
    for (int i = 0; i < 7; i++) {
        int h = blockIdx.y * 7 + i;
        size_t base = ((size_t)s * NH + h) * HD;
        float x  = g_q[base + d];
        float xo = g_q[base + (d ^ 64)];
        g_qt[base + dp] = __float2half_rn(fmaf(sg * xo, sn, x * c));
    }
    {
        size_t base = ((size_t)s * NKV + blockIdx.y) * HD;
        float x  = g_k[base + d];
        float xo = g_k[base + (d ^ 64)];
        g_kt[base + dp] = __float2half_rn(fmaf(sg * xo, sn, x * c));
    }
}

// ---------------- FP16 tensor GEMM: C = A[M,K]*B[N,K]^T + bias ---------------
// 128x128 block, 256 threads (8 warps), warp 64x32, BK=64 halves, 3 stages.
#define GSTRh 72                       // halves per smem row (64 + 8 pad)
#define GSTAGEh (128 * GSTRh)
#define GEMM_SMEM (3 * GSTAGEh * 2 * 2)   // bytes

// MODE: 0 = fp32 out + bias, 1 = V: fp16 transposed+perm out + bias, 2 = fp32 no bias
template <int MODE>
__device__ __forceinline__ void gemm_body(
    const __half* __restrict__ A, const __half* __restrict__ B,
    const float* __restrict__ bias, void* __restrict__ C,
    int N, int K, int bx, int by, __half* As, __half* Bs)
{
    const int tid  = threadIdx.x;
    const int warp = tid >> 5, lane = tid & 31;
    const int g = lane >> 2, tg = lane & 3;
    const int wm = (warp >> 2) * 64;
    const int wn = (warp & 3) * 32;

    float acc[16][4];
#pragma unroll
    for (int i = 0; i < 16; i++)
#pragma unroll
        for (int j = 0; j < 4; j++) acc[i][j] = 0.f;

    const int T = K / 64;

#define LOAD_TILE(t_)                                                            \
    do {                                                                         \
        __half* ab_ = As + ((t_) % 3) * GSTAGEh;                                 \
        __half* bb_ = Bs + ((t_) % 3) * GSTAGEh;                                 \
        _Pragma("unroll")                                                        \
        for (int i_ = 0; i_ < 4; i_++) {                                         \
            int f_ = tid + i_ * 256;                                             \
            int row_ = f_ >> 3, ch_ = (f_ & 7) * 8;                              \
            cp16(smem_u32(ab_ + row_ * GSTRh + ch_),                             \
                 A + (size_t)(by * 128 + row_) * K + (t_) * 64 + ch_);           \
            cp16(smem_u32(bb_ + row_ * GSTRh + ch_),                             \
                 B + (size_t)(bx * 128 + row_) * K + (t_) * 64 + ch_);           \
        }                                                                        \
        CP_COMMIT();                                                             \
    } while (0)

    LOAD_TILE(0);
    LOAD_TILE(1);

    for (int t = 0; t < T; t++) {
        if (t < T - 1) CP_WAIT(1); else CP_WAIT(0);
        __syncthreads();

        if (t + 2 < T) LOAD_TILE(t + 2);

        const __half* as = As + (t % 3) * GSTAGEh;
        const __half* bs = Bs + (t % 3) * GSTAGEh;
#pragma unroll
        for (int kk = 0; kk < 64; kk += 16) {
            uint32_t a[4][4], bf[4][2];
#pragma unroll
            for (int mt = 0; mt < 4; mt++) {
                int r = wm + mt * 16;
                uint2 x = *(const uint2*)(as + (r + g) * GSTRh + kk + 4 * tg);
                uint2 y = *(const uint2*)(as + (r + 8 + g) * GSTRh + kk + 4 * tg);
                a[mt][0] = x.x; a[mt][1] = y.x; a[mt][2] = x.y; a[mt][3] = y.y;
            }
#pragma unroll
            for (int nt = 0; nt < 4; nt++) {
                uint2 u = *(const uint2*)(bs + (wn + nt * 8 + g) * GSTRh + kk + 4 * tg);
                bf[nt][0] = u.x; bf[nt][1] = u.y;
            }
#pragma unroll
            for (int mt = 0; mt < 4; mt++)
#pragma unroll
                for (int nt = 0; nt < 4; nt++)
                    mma_f16(acc[mt * 4 + nt], a[mt], bf[nt]);
        }
    }
    __syncthreads();

#pragma unroll
    for (int mt = 0; mt < 4; mt++) {
#pragma unroll
        for (int nt = 0; nt < 4; nt++) {
            int r0 = by * 128 + wm + mt * 16 + g;
            int c0 = bx * 128 + wn + nt * 8 + 2 * tg;
            float b0 = (MODE != 2) ? bias[c0] : 0.f;
            float b1 = (MODE != 2) ? bias[c0 + 1] : 0.f;
            float* ca = acc[mt * 4 + nt];
            if (MODE == 1) {
                __half* Co = (__half*)C;   // g_vtT: [c][perm16(s)]
                int sp0 = perm16(r0), sp1 = perm16(r0 + 8);
                Co[(size_t)c0 * SEQ + sp0]       = __float2half_rn(ca[0] + b0);
                Co[(size_t)(c0 + 1) * SEQ + sp0] = __float2half_rn(ca[1] + b1);
                Co[(size_t)c0 * SEQ + sp1]       = __float2half_rn(ca[2] + b0);
                Co[(size_t)(c0 + 1) * SEQ + sp1] = __float2half_rn(ca[3] + b1);
            } else {
                float* Co = (float*)C;
                *(float2*)(&Co[(size_t)r0 * N + c0])       = make_float2(ca[0] + b0, ca[1] + b1);
                *(float2*)(&Co[(size_t)(r0 + 8) * N + c0]) = make_float2(ca[2] + b0, ca[3] + b1);
            }
        }
    }
#undef LOAD_TILE
}

__global__ __launch_bounds__(256) void gemm_qkv(
    const float* __restrict__ bq, const float* __restrict__ bk,
    const float* __restrict__ bv)
{
    extern __shared__ __half gsm[];
    __half* As = gsm;
    __half* Bs = gsm + 3 * GSTAGEh;
    const int bx = blockIdx.x, by = blockIdx.y;
    if (bx < 28)
        gemm_body<0>(g_hid_t, g_wq_t, bq, g_q, NH * HD, HID, bx, by, As, Bs);
    else if (bx < 32)
        gemm_body<0>(g_hid_t, g_wk_t, bk, g_k, NKV * HD, HID, bx - 28, by, As, Bs);
    else
        gemm_body<1>(g_hid_t, g_wv_t, bv, g_vtT, NKV * HD, HID, bx - 32, by, As, Bs);
}

__global__ __launch_bounds__(256) void gemm_out(float* __restrict__ C)
{
    extern __shared__ __half gsm[];
    gemm_body<2>(g_ot, g_wo_t, nullptr, C, HID, HID, blockIdx.x, blockIdx.y,
                 gsm, gsm + 3 * GSTAGEh);
}

// ---------------- Flash attention (FP16 mma, fp32 softmax, pipelined) --------
// BQ=128, BKV=64. 8 warps; warp owns 16 query rows. K double-buffered,
// V^T single-buffered. ~107KB smem -> 2 CTAs/SM.
#define QSTRh 136
#define KSTRh 136
#define VTSTRh 72
#define PSTRh 72
#define KVTILEh (64 * KSTRh)
#define FLASH_SMEM ((128*QSTRh + 2*KVTILEh + 128*VTSTRh + 128*PSTRh) * 2 + 64 * 4)

__global__ __launch_bounds__(256) void flash_kernel(const int* __restrict__ doc)
{
    extern __shared__ __half fsm[];
    __half* Qs  = fsm;                        // [128][QSTRh] permuted d
    __half* Ks  = Qs + 128 * QSTRh;           // 2 x [64][KSTRh] permuted d
    __half* VTs = Ks + 2 * KVTILEh;           // [128 d][VTSTRh] permuted key
    __half* Ps  = VTs + 128 * VTSTRh;         // [128][PSTRh] permuted key
    int* kdoc = (int*)(Ps + 128 * PSTRh);

    const int qb = gridDim.x - 1 - blockIdx.x;
    const int head = blockIdx.y;
    const int kvh = head / GRP;
    const int q0 = qb * 128;
    const int tid = threadIdx.x;
    const int warp = tid >> 5, lane = tid & 31;
    const int g = lane >> 2, tg = lane & 3;
    const int m0 = warp * 16;

    // prologue: Q group, K0 group, VT0 group
    for (int f = tid; f < 128 * 16; f += 256) {
        int row = f >> 4, c8 = (f & 15) * 8;
        cp16(smem_u32(Qs + row * QSTRh + c8),
             g_qt + ((size_t)(q0 + row) * NH + head) * HD + c8);
    }
    CP_COMMIT();
    for (int f = tid; f < 64 * 16; f += 256) {
        int row = f >> 4, c8 = (f & 15) * 8;
        cp16(smem_u32(Ks + row * KSTRh + c8),
             g_kt + ((size_t)row * NKV + kvh) * HD + c8);
    }
    CP_COMMIT();
    for (int f = tid; f < 128 * 8; f += 256) {
        int d = f >> 3, c8 = (f & 7) * 8;
        cp16(smem_u32(VTs + d * VTSTRh + c8),
             g_vtT + ((size_t)(kvh * HD + d)) * SEQ + c8);
    }
    CP_COMMIT();

    const int qr0 = q0 + m0 + g, qr1 = qr0 + 8;
    const int qd0 = doc[qr0], qd1 = doc[qr1];
    float mi0 = -1e30f, mi1 = -1e30f, li0 = 0.f, li1 = 0.f;
    float o[16][4];
#pragma unroll
    for (int i = 0; i < 16; i++)
#pragma unroll
        for (int j = 0; j < 4; j++) o[i][j] = 0.f;

    const int tmax = 2 * qb + 1;
    for (int t = 0; t <= tmax; t++) {
        const int k0 = t * 64;
        if (tid < 64) kdoc[tid] = doc[k0 + tid];
        CP_WAIT(1);                 // Q + K_t done (VT_t may pend)
        __syncthreads();

        const __half* ks = Ks + (t & 1) * KVTILEh;

        // scores: warp m16 x n64 x k128 (8 k16 steps)
        float s[8][4];
#pragma unroll
        for (int i = 0; i < 8; i++)
#pragma unroll
            for (int j = 0; j < 4; j++) s[i][j] = 0.f;

#pragma unroll
        for (int kk = 0; kk < 128; kk += 16) {
            uint32_t a[4];
            uint2 x = *(const uint2*)(Qs + (m0 + g) * QSTRh + kk + 4 * tg);
            uint2 y = *(const uint2*)(Qs + (m0 + 8 + g) * QSTRh + kk + 4 * tg);
            a[0] = x.x; a[1] = y.x; a[2] = x.y; a[3] = y.y;
#pragma unroll
            for (int nt = 0; nt < 8; nt++) {
                uint2 u = *(const uint2*)(ks + (nt * 8 + g) * KSTRh + kk + 4 * tg);
                uint32_t bf[2] = {u.x, u.y};
                mma_f16(s[nt], a, bf);
            }
        }

        // mask + scale + row max
        float mx0 = -1e30f, mx1 = -1e30f;
#pragma unroll
        for (int nt = 0; nt < 8; nt++) {
            int c0 = k0 + nt * 8 + 2 * tg;
            int d0 = kdoc[nt * 8 + 2 * tg];
            int d1 = kdoc[nt * 8 + 2 * tg + 1];
            s[nt][0] = (qr0 >= c0     && qd0 == d0) ? s[nt][0] * SOFT_SCALE : -1e30f;
            s[nt][1] = (qr0 >= c0 + 1 && qd0 == d1) ? s[nt][1] * SOFT_SCALE : -1e30f;
            s[nt][2] = (qr1 >= c0     && qd1 == d0) ? s[nt][2] * SOFT_SCALE : -1e30f;
            s[nt][3] = (qr1 >= c0 + 1 && qd1 == d1) ? s[nt][3] * SOFT_SCALE : -1e30f;
            mx0 = fmaxf(mx0, fmaxf(s[nt][0], s[nt][1]));
            mx1 = fmaxf(mx1, fmaxf(s[nt][2], s[nt][3]));
        }
        mx0 = fmaxf(mx0, __shfl_xor_sync(0xffffffffu, mx0, 1));
        mx0 = fmaxf(mx0, __shfl_xor_sync(0xffffffffu, mx0, 2));
        mx1 = fmaxf(mx1, __shfl_xor_sync(0xffffffffu, mx1, 1));
        mx1 = fmaxf(mx1, __shfl_xor_sync(0xffffffffu, mx1, 2));

        float nm0 = fmaxf(mi0, mx0), nm1 = fmaxf(mi1, mx1);
        float cr0 = __expf(mi0 - nm0), cr1 = __expf(mi1 - nm1);
        mi0 = nm0; mi1 = nm1;
#pragma unroll
        for (int nt = 0; nt < 16; nt++) {
            o[nt][0] *= cr0; o[nt][1] *= cr0;
            o[nt][2] *= cr1; o[nt][3] *= cr1;
        }

        float rs0 = 0.f, rs1 = 0.f;
#pragma unroll
        for (int nt = 0; nt < 8; nt++) {
            float pe0 = (s[nt][0] > -1e29f) ? __expf(s[nt][0] - nm0) : 0.f;
            float pe1 = (s[nt][1] > -1e29f) ? __expf(s[nt][1] - nm0) : 0.f;
            float pe2 = (s[nt][2] > -1e29f) ? __expf(s[nt][2] - nm1) : 0.f;
            float pe3 = (s[nt][3] > -1e29f) ? __expf(s[nt][3] - nm1) : 0.f;
            rs0 += pe0 + pe1; rs1 += pe2 + pe3;
            // write half2 pair at permuted position
            int c = nt * 8 + 2 * tg;
            int p = (c >> 1) & 7;
            int hp = (c & ~15) | (((((p & 3) << 1) | (p >> 2))) << 1);
            *(__half2*)(Ps + (m0 + g) * PSTRh + hp)     = __floats2half2_rn(pe0, pe1);
            *(__half2*)(Ps + (m0 + 8 + g) * PSTRh + hp) = __floats2half2_rn(pe2, pe3);
        }
        rs0 += __shfl_xor_sync(0xffffffffu, rs0, 1);
        rs0 += __shfl_xor_sync(0xffffffffu, rs0, 2);
        rs1 += __shfl_xor_sync(0xffffffffu, rs1, 1);
        rs1 += __shfl_xor_sync(0xffffffffu, rs1, 2);
        li0 = li0 * cr0 + rs0;
        li1 = li1 * cr1 + rs1;

        // prefetch K_{t+1}; then wait own VT_t
        if (t < tmax) {
            const int kn = k0 + 64;
            __half* kd = Ks + ((t + 1) & 1) * KVTILEh;
            for (int f = tid; f < 64 * 16; f += 256) {
                int row = f >> 4, c8 = (f & 15) * 8;
                cp16(smem_u32(kd + row * KSTRh + c8),
                     g_kt + ((size_t)(kn + row) * NKV + kvh) * HD + c8);
            }
            CP_COMMIT();
            CP_WAIT(1);             // VT_t done (K_{t+1} pending)
        } else {
            CP_WAIT(0);
        }
        __syncthreads();            // VT_t + Ps visible

        // O += P * V : warp m16 x n128 x k64 (4 k16 steps)
#pragma unroll
        for (int kk = 0; kk < 64; kk += 16) {
            uint32_t a[4];
            uint2 x = *(const uint2*)(Ps + (m0 + g) * PSTRh + kk + 4 * tg);
            uint2 y = *(const uint2*)(Ps + (m0 + 8 + g) * PSTRh + kk + 4 * tg);
            a[0] = x.x; a[1] = y.x; a[2] = x.y; a[3] = y.y;
#pragma unroll
            for (int nt = 0; nt < 16; nt++) {
                uint2 u = *(const uint2*)(VTs + (nt * 8 + g) * VTSTRh + kk + 4 * tg);
                uint32_t bf[2] = {u.x, u.y};
                mma_f16(o[nt], a, bf);
            }
        }
        __syncthreads();            // PV done everywhere

        // issue VT_{t+1}
        if (t < tmax) {
            const int kn = k0 + 64;
            for (int f = tid; f < 128 * 8; f += 256) {
                int d = f >> 3, c8 = (f & 7) * 8;
                cp16(smem_u32(VTs + d * VTSTRh + c8),
                     g_vtT + ((size_t)(kvh * HD + d)) * SEQ + kn + c8);
            }
            CP_COMMIT();
        }
    }

    // normalize + write k-permuted fp16 (A operand of O projection)
    float inv0 = 1.f / li0, inv1 = 1.f / li1;
#pragma unroll
    for (int nt = 0; nt < 16; nt++) {
        int c = nt * 8 + 2 * tg;
        int p = (c >> 1) & 7;
        int hp = (c & ~15) | (((((p & 3) << 1) | (p >> 2))) << 1);
        size_t b0 = ((size_t)qr0 * NH + head) * HD + hp;
        size_t b1 = ((size_t)qr1 * NH + head) * HD + hp;
        *(__half2*)(g_ot + b0) = __floats2half2_rn(o[nt][0] * inv0, o[nt][1] * inv0);
        *(__half2*)(g_ot + b1) = __floats2half2_rn(o[nt][2] * inv1, o[nt][3] * inv1);
    }
}

// ---------------- launch -----------------------------------------------------
extern "C" void kernel_launch(void* const* d_in, const int* in_sizes, int n_in,
                              void* d_out, int out_size)
{
    const float* hidden = (const float*)d_in[0];
    const float* cosT   = (const float*)d_in[1];
    const float* sinT   = (const float*)d_in[2];
    const int*   doc    = (const int*)  d_in[3];
    const float* Wq = (const float*)d_in[5];
    const float* bq = (const float*)d_in[6];
    const float* Wk = (const float*)d_in[7];
    const float* bk = (const float*)d_in[8];
    const float* Wv = (const float*)d_in[9];
    const float* bv = (const float*)d_in[10];
    const float* Wo = (const float*)d_in[11];
    float* out = (float*)d_out;

    void *hid_t, *wq_t, *wk_t, *wv_t, *wo_t;
    cudaGetSymbolAddress(&hid_t, g_hid_t);
    cudaGetSymbolAddress(&wq_t, g_wq_t);
    cudaGetSymbolAddress(&wk_t, g_wk_t);
    cudaGetSymbolAddress(&wv_t, g_wv_t);
    cudaGetSymbolAddress(&wo_t, g_wo_t);

    // 1) fp32 -> fp16 + pair-interleave for hidden + weights
    {
        struct { const void* s; void* d; int n; } cv[5] = {
            {hidden, hid_t, SEQ * HID},
            {Wq, wq_t, NH * HD * HID},
            {Wk, wk_t, NKV * HD * HID},
            {Wv, wv_t, NKV * HD * HID},
            {Wo, wo_t, HID * NH * HD},
        };
        for (int i = 0; i < 5; i++) {
            int nt = cv[i].n / 8;
            conv_h<<<(nt + 255) / 256, 256>>>((const float*)cv[i].s,
                                              (__half*)cv[i].d, cv[i].n);
        }
    }

    // 2) fused QKV projections (fp16 HMMA; V written transposed fp16)
    cudaFuncSetAttribute(gemm_qkv, cudaFuncAttributeMaxDynamicSharedMemorySize, GEMM_SMEM);
    gemm_qkv<<<dim3(36, SEQ / 128), 256, GEMM_SMEM>>>(bq, bk, bv);

    // 3) RoPE + fp16 + permute for Q/K
    prep_rope<<<dim3(SEQ, 4), HD>>>(cosT, sinT);

    // 4) flash attention (fp16 HMMA)
    cudaFuncSetAttribute(flash_kernel, cudaFuncAttributeMaxDynamicSharedMemorySize, FLASH_SMEM);
    flash_kernel<<<dim3(SEQ / 128, NH), 256, FLASH_SMEM>>>(doc);

    // 5) output projection
    cudaFuncSetAttribute(gemm_out, cudaFuncAttributeMaxDynamicSharedMemorySize, GEMM_SMEM);
    gemm_out<<<dim3(HID / 128, SEQ / 128), 256, GEMM_SMEM>>>(out);
}

// round 11
// speedup vs baseline: 9.5477x; 1.3309x over previous
#include <cuda_runtime.h>
#include <cuda_fp16.h>
#include <math.h>
#include <stdint.h>

#define SEQ 2048
#define HID 3584
#define NH 28
#define NKV 4
#define GRP 7
#define HD 128
#define SOFT_SCALE 0.08838834764831845f   // 1/sqrt(128)

// ---------------- scratch (static device globals; no runtime allocation) ----
// All fp16 arrays are NATURAL K-major layout (ldmatrix handles fragment shuffle).
__device__ __half g_hid_t[SEQ * HID];
__device__ __half g_wq_t[NH * HD * HID];
__device__ __half g_wk_t[NKV * HD * HID];
__device__ __half g_wv_t[NKV * HD * HID];
__device__ __half g_wo_t[HID * NH * HD];
__device__ float  g_q[SEQ * NH * HD];        // Q pre-rope fp32
__device__ float  g_k[SEQ * NKV * HD];       // K pre-rope fp32
__device__ __half g_qt[SEQ * NH * HD];       // rope(Q) fp16
__device__ __half g_kt[SEQ * NKV * HD];      // rope(K) fp16
__device__ __half g_vtT[NKV * HD * SEQ];     // V fp16 TRANSPOSED [h*d][s]
__device__ __half g_ot[SEQ * NH * HD];       // attn out fp16

// ---------------- helpers ----------------------------------------------------
__device__ __forceinline__ void mma_f16(float* c, const uint32_t* a, const uint32_t* b) {
    asm volatile(
        "mma.sync.aligned.m16n8k16.row.col.f32.f16.f16.f32 "
        "{%0,%1,%2,%3}, {%4,%5,%6,%7}, {%8,%9}, {%0,%1,%2,%3};"
        : "+f"(c[0]), "+f"(c[1]), "+f"(c[2]), "+f"(c[3])
        : "r"(a[0]), "r"(a[1]), "r"(a[2]), "r"(a[3]), "r"(b[0]), "r"(b[1]));
}
__device__ __forceinline__ void ldsm4(uint32_t* r, uint32_t addr) {
    asm volatile("ldmatrix.sync.aligned.m8n8.x4.shared.b16 {%0,%1,%2,%3}, [%4];"
        : "=r"(r[0]), "=r"(r[1]), "=r"(r[2]), "=r"(r[3]) : "r"(addr));
}
__device__ __forceinline__ uint32_t smem_u32(const void* p) {
    return (uint32_t)__cvta_generic_to_shared(p);
}
__device__ __forceinline__ void cp16(uint32_t s, const void* g) {
    asm volatile("cp.async.cg.shared.global [%0], [%1], 16;" :: "r"(s), "l"(g));
}
#define CP_COMMIT() asm volatile("cp.async.commit_group;" ::: "memory")
#define CP_WAIT(n)  asm volatile("cp.async.wait_group %0;" :: "n"(n) : "memory")

// ---------------- single fused fp32 -> fp16 converter ------------------------
#define CN0 ((long)SEQ * HID)
#define CN1 ((long)NH * HD * HID)
#define CN2 ((long)NKV * HD * HID)
#define CTOT (CN0 + CN1 + 2 * CN2 + CN1)

__global__ void conv_all(const float* __restrict__ h, const float* __restrict__ wq,
                         const float* __restrict__ wk, const float* __restrict__ wv,
                         const float* __restrict__ wo)
{
    long i = ((long)blockIdx.x * blockDim.x + threadIdx.x) * 8;
    const float* s; __half* d; long off;
    if (i < CN0)                       { s = h;  d = g_hid_t; off = i; }
    else if (i < CN0 + CN1)            { s = wq; d = g_wq_t;  off = i - CN0; }
    else if (i < CN0 + CN1 + CN2)      { s = wk; d = g_wk_t;  off = i - CN0 - CN1; }
    else if (i < CN0 + CN1 + 2 * CN2)  { s = wv; d = g_wv_t;  off = i - CN0 - CN1 - CN2; }
    else                               { s = wo; d = g_wo_t;  off = i - CN0 - CN1 - 2 * CN2; }
    float4 x = *(const float4*)(s + off);
    float4 y = *(const float4*)(s + off + 4);
    __half hh[8] = { __float2half_rn(x.x), __float2half_rn(x.y),
                     __float2half_rn(x.z), __float2half_rn(x.w),
                     __float2half_rn(y.x), __float2half_rn(y.y),
                     __float2half_rn(y.z), __float2half_rn(y.w) };
    *(uint4*)(d + off) = *(uint4*)hh;
}

// ---------------- rope + fp16 (natural layout) -------------------------------
__global__ void prep_rope(const float* __restrict__ cosT, const float* __restrict__ sinT)
{
    const int s = blockIdx.x, d = threadIdx.x;
    const float c  = cosT[s * HD + d];
    const float sn = sinT[s * HD + d];
    const float sg = (d < 64) ? -1.f : 1.f;

#pragma unroll
    for (int i = 0; i < 7; i++) {
        int h = blockIdx.y * 7 + i;
        size_t base = ((size_t)s * NH + h) * HD;
        float x  = g_q[base + d];
        float xo = g_q[base + (d ^ 64)];
        g_qt[base + d] = __float2half_rn(fmaf(sg * xo, sn, x * c));
    }
    {
        size_t base = ((size_t)s * NKV + blockIdx.y) * HD;
        float x  = g_k[base + d];
        float xo = g_k[base + (d ^ 64)];
        g_kt[base + d] = __float2half_rn(fmaf(sg * xo, sn, x * c));
    }
}

// ---------------- FP16 tensor GEMM: C = A[M,K]*B[N,K]^T + bias ---------------
// 128x128 block, 256 threads (8 warps), warp 64x32, BK=64 halves, 3 stages.
// ldmatrix fragment loads (natural K-major; stride 144B => conflict-free).
#define GSTRh 72
#define GSTAGEh (128 * GSTRh)
#define GEMM_SMEM (3 * GSTAGEh * 2 * 2)   // bytes

// MODE: 0 = fp32 out + bias, 1 = V: fp16 transposed out + bias, 2 = fp32 no bias
template <int MODE>
__device__ __forceinline__ void gemm_body(
    const __half* __restrict__ A, const __half* __restrict__ B,
    const float* __restrict__ bias, void* __restrict__ C,
    int N, int K, int bx, int by, __half* As, __half* Bs)
{
    const int tid  = threadIdx.x;
    const int warp = tid >> 5, lane = tid & 31;
    const int g = lane >> 2, tg = lane & 3;
    const int wm = (warp >> 2) * 64;
    const int wn = (warp & 3) * 32;
    // ldmatrix lane addressing
    const int arow = lane & 15, acol = (lane >> 4) << 3;           // A/x4: 2 k-halves
    const int brow = lane & 7, bk8 = ((lane >> 3) & 1) << 3;       // B/x4: 2 n-tiles
    const int bnt  = lane >> 4;

    float acc[16][4];
#pragma unroll
    for (int i = 0; i < 16; i++)
#pragma unroll
        for (int j = 0; j < 4; j++) acc[i][j] = 0.f;

    const int T = K / 64;

#define LOAD_TILE(t_)                                                            \
    do {                                                                         \
        __half* ab_ = As + ((t_) % 3) * GSTAGEh;                                 \
        __half* bb_ = Bs + ((t_) % 3) * GSTAGEh;                                 \
        _Pragma("unroll")                                                        \
        for (int i_ = 0; i_ < 4; i_++) {                                         \
            int f_ = tid + i_ * 256;                                             \
            int row_ = f_ >> 3, ch_ = (f_ & 7) * 8;                              \
            cp16(smem_u32(ab_ + row_ * GSTRh + ch_),                             \
                 A + (size_t)(by * 128 + row_) * K + (t_) * 64 + ch_);           \
            cp16(smem_u32(bb_ + row_ * GSTRh + ch_),                             \
                 B + (size_t)(bx * 128 + row_) * K + (t_) * 64 + ch_);           \
        }                                                                        \
        CP_COMMIT();                                                             \
    } while (0)

    LOAD_TILE(0);
    LOAD_TILE(1);

    for (int t = 0; t < T; t++) {
        if (t < T - 1) CP_WAIT(1); else CP_WAIT(0);
        __syncthreads();

        if (t + 2 < T) LOAD_TILE(t + 2);

        const __half* as = As + (t % 3) * GSTAGEh;
        const __half* bs = Bs + (t % 3) * GSTAGEh;
#pragma unroll
        for (int kk = 0; kk < 64; kk += 16) {
            uint32_t a[4][4], bb[2][4];
#pragma unroll
            for (int mt = 0; mt < 4; mt++)
                ldsm4(a[mt], smem_u32(as + (wm + mt * 16 + arow) * GSTRh + kk + acol));
#pragma unroll
            for (int np = 0; np < 2; np++)
                ldsm4(bb[np], smem_u32(bs + (wn + (np * 2 + bnt) * 8 + brow) * GSTRh + kk + bk8));
#pragma unroll
            for (int mt = 0; mt < 4; mt++)
#pragma unroll
                for (int nt = 0; nt < 4; nt++)
                    mma_f16(acc[mt * 4 + nt], a[mt], &bb[nt >> 1][(nt & 1) * 2]);
        }
    }
    __syncthreads();

#pragma unroll
    for (int mt = 0; mt < 4; mt++) {
#pragma unroll
        for (int nt = 0; nt < 4; nt++) {
            int r0 = by * 128 + wm + mt * 16 + g;
            int c0 = bx * 128 + wn + nt * 8 + 2 * tg;
            float b0 = (MODE != 2) ? bias[c0] : 0.f;
            float b1 = (MODE != 2) ? bias[c0 + 1] : 0.f;
            float* ca = acc[mt * 4 + nt];
            if (MODE == 1) {
                __half* Co = (__half*)C;   // g_vtT: [c][s]
                Co[(size_t)c0 * SEQ + r0]           = __float2half_rn(ca[0] + b0);
                Co[(size_t)(c0 + 1) * SEQ + r0]     = __float2half_rn(ca[1] + b1);
                Co[(size_t)c0 * SEQ + r0 + 8]       = __float2half_rn(ca[2] + b0);
                Co[(size_t)(c0 + 1) * SEQ + r0 + 8] = __float2half_rn(ca[3] + b1);
            } else {
                float* Co = (float*)C;
                *(float2*)(&Co[(size_t)r0 * N + c0])       = make_float2(ca[0] + b0, ca[1] + b1);
                *(float2*)(&Co[(size_t)(r0 + 8) * N + c0]) = make_float2(ca[2] + b0, ca[3] + b1);
            }
        }
    }
#undef LOAD_TILE
}

__global__ __launch_bounds__(256) void gemm_qkv(
    const float* __restrict__ bq, const float* __restrict__ bk,
    const float* __restrict__ bv)
{
    extern __shared__ __align__(16) __half gsm[];
    __half* As = gsm;
    __half* Bs = gsm + 3 * GSTAGEh;
    const int bx = blockIdx.x, by = blockIdx.y;
    if (bx < 28)
        gemm_body<0>(g_hid_t, g_wq_t, bq, g_q, NH * HD, HID, bx, by, As, Bs);
    else if (bx < 32)
        gemm_body<0>(g_hid_t, g_wk_t, bk, g_k, NKV * HD, HID, bx - 28, by, As, Bs);
    else
        gemm_body<1>(g_hid_t, g_wv_t, bv, g_vtT, NKV * HD, HID, bx - 32, by, As, Bs);
}

__global__ __launch_bounds__(256) void gemm_out(float* __restrict__ C)
{
    extern __shared__ __align__(16) __half gsm[];
    gemm_body<2>(g_ot, g_wo_t, nullptr, C, HID, HID, blockIdx.x, blockIdx.y,
                 gsm, gsm + 3 * GSTAGEh);
}

// ---------------- Flash attention (FP16 mma + ldmatrix, fp32 softmax) --------
// BQ=128, BKV=64. 8 warps; warp owns 16 query rows. K double-buffered,
// V^T single-buffered. ~107KB smem -> 2 CTAs/SM.
#define QSTRh 136
#define KSTRh 136
#define VTSTRh 72
#define PSTRh 72
#define KVTILEh (64 * KSTRh)
#define FLASH_SMEM ((128*QSTRh + 2*KVTILEh + 128*VTSTRh + 128*PSTRh) * 2 + 64 * 4)

__global__ __launch_bounds__(256) void flash_kernel(const int* __restrict__ doc)
{
    extern __shared__ __align__(16) __half fsm[];
    __half* Qs  = fsm;                        // [128][QSTRh]
    __half* Ks  = Qs + 128 * QSTRh;           // 2 x [64][KSTRh]
    __half* VTs = Ks + 2 * KVTILEh;           // [128 d][VTSTRh]
    __half* Ps  = VTs + 128 * VTSTRh;         // [128][PSTRh]
    int* kdoc = (int*)(Ps + 128 * PSTRh);

    const int qb = gridDim.x - 1 - blockIdx.x;
    const int head = blockIdx.y;
    const int kvh = head / GRP;
    const int q0 = qb * 128;
    const int tid = threadIdx.x;
    const int warp = tid >> 5, lane = tid & 31;
    const int g = lane >> 2, tg = lane & 3;
    const int m0 = warp * 16;
    const int arow = lane & 15, acol = (lane >> 4) << 3;
    const int brow = lane & 7, bk8 = ((lane >> 3) & 1) << 3;
    const int bnt  = lane >> 4;

    // prologue: Q group, K0 group, VT0 group
    for (int f = tid; f < 128 * 16; f += 256) {
        int row = f >> 4, c8 = (f & 15) * 8;
        cp16(smem_u32(Qs + row * QSTRh + c8),
             g_qt + ((size_t)(q0 + row) * NH + head) * HD + c8);
    }
    CP_COMMIT();
    for (int f = tid; f < 64 * 16; f += 256) {
        int row = f >> 4, c8 = (f & 15) * 8;
        cp16(smem_u32(Ks + row * KSTRh + c8),
             g_kt + ((size_t)row * NKV + kvh) * HD + c8);
    }
    CP_COMMIT();
    for (int f = tid; f < 128 * 8; f += 256) {
        int d = f >> 3, c8 = (f & 7) * 8;
        cp16(smem_u32(VTs + d * VTSTRh + c8),
             g_vtT + ((size_t)(kvh * HD + d)) * SEQ + c8);
    }
    CP_COMMIT();

    const int qr0 = q0 + m0 + g, qr1 = qr0 + 8;
    const int qd0 = doc[qr0], qd1 = doc[qr1];
    float mi0 = -1e30f, mi1 = -1e30f, li0 = 0.f, li1 = 0.f;
    float o[16][4];
#pragma unroll
    for (int i = 0; i < 16; i++)
#pragma unroll
        for (int j = 0; j < 4; j++) o[i][j] = 0.f;

    const int tmax = 2 * qb + 1;
    for (int t = 0; t <= tmax; t++) {
        const int k0 = t * 64;
        if (tid < 64) kdoc[tid] = doc[k0 + tid];
        CP_WAIT(1);                 // Q + K_t done (VT_t may pend)
        __syncthreads();

        const __half* ks = Ks + (t & 1) * KVTILEh;

        // scores: warp m16 x n64 x k128
        float s[8][4];
#pragma unroll
        for (int i = 0; i < 8; i++)
#pragma unroll
            for (int j = 0; j < 4; j++) s[i][j] = 0.f;

#pragma unroll
        for (int kk = 0; kk < 128; kk += 16) {
            uint32_t a[4];
            ldsm4(a, smem_u32(Qs + (m0 + arow) * QSTRh + kk + acol));
#pragma unroll
            for (int np = 0; np < 4; np++) {
                uint32_t bb[4];
                ldsm4(bb, smem_u32(ks + ((np * 2 + bnt) * 8 + brow) * KSTRh + kk + bk8));
                mma_f16(s[np * 2 + 0], a, bb);
                mma_f16(s[np * 2 + 1], a, bb + 2);
            }
        }

        // mask + scale + row max
        float mx0 = -1e30f, mx1 = -1e30f;
#pragma unroll
        for (int nt = 0; nt < 8; nt++) {
            int c0 = k0 + nt * 8 + 2 * tg;
            int d0 = kdoc[nt * 8 + 2 * tg];
            int d1 = kdoc[nt * 8 + 2 * tg + 1];
            s[nt][0] = (qr0 >= c0     && qd0 == d0) ? s[nt][0] * SOFT_SCALE : -1e30f;
            s[nt][1] = (qr0 >= c0 + 1 && qd0 == d1) ? s[nt][1] * SOFT_SCALE : -1e30f;
            s[nt][2] = (qr1 >= c0     && qd1 == d0) ? s[nt][2] * SOFT_SCALE : -1e30f;
            s[nt][3] = (qr1 >= c0 + 1 && qd1 == d1) ? s[nt][3] * SOFT_SCALE : -1e30f;
            mx0 = fmaxf(mx0, fmaxf(s[nt][0], s[nt][1]));
            mx1 = fmaxf(mx1, fmaxf(s[nt][2], s[nt][3]));
        }
        mx0 = fmaxf(mx0, __shfl_xor_sync(0xffffffffu, mx0, 1));
        mx0 = fmaxf(mx0, __shfl_xor_sync(0xffffffffu, mx0, 2));
        mx1 = fmaxf(mx1, __shfl_xor_sync(0xffffffffu, mx1, 1));
        mx1 = fmaxf(mx1, __shfl_xor_sync(0xffffffffu, mx1, 2));

        float nm0 = fmaxf(mi0, mx0), nm1 = fmaxf(mi1, mx1);
        float cr0 = __expf(mi0 - nm0), cr1 = __expf(mi1 - nm1);
        mi0 = nm0; mi1 = nm1;
#pragma unroll
        for (int nt = 0; nt < 16; nt++) {
            o[nt][0] *= cr0; o[nt][1] *= cr0;
            o[nt][2] *= cr1; o[nt][3] *= cr1;
        }

        float rs0 = 0.f, rs1 = 0.f;
#pragma unroll
        for (int nt = 0; nt < 8; nt++) {
            float pe0 = (s[nt][0] > -1e29f) ? __expf(s[nt][0] - nm0) : 0.f;
            float pe1 = (s[nt][1] > -1e29f) ? __expf(s[nt][1] - nm0) : 0.f;
            float pe2 = (s[nt][2] > -1e29f) ? __expf(s[nt][2] - nm1) : 0.f;
            float pe3 = (s[nt][3] > -1e29f) ? __expf(s[nt][3] - nm1) : 0.f;
            rs0 += pe0 + pe1; rs1 += pe2 + pe3;
            int c = nt * 8 + 2 * tg;
            *(__half2*)(Ps + (m0 + g) * PSTRh + c)     = __floats2half2_rn(pe0, pe1);
            *(__half2*)(Ps + (m0 + 8 + g) * PSTRh + c) = __floats2half2_rn(pe2, pe3);
        }
        rs0 += __shfl_xor_sync(0xffffffffu, rs0, 1);
        rs0 += __shfl_xor_sync(0xffffffffu, rs0, 2);
        rs1 += __shfl_xor_sync(0xffffffffu, rs1, 1);
        rs1 += __shfl_xor_sync(0xffffffffu, rs1, 2);
        li0 = li0 * cr0 + rs0;
        li1 = li1 * cr1 + rs1;

        // prefetch K_{t+1}; then wait own VT_t
        if (t < tmax) {
            const int kn = k0 + 64;
            __half* kd = Ks + ((t + 1) & 1) * KVTILEh;
            for (int f = tid; f < 64 * 16; f += 256) {
                int row = f >> 4, c8 = (f & 15) * 8;
                cp16(smem_u32(kd + row * KSTRh + c8),
                     g_kt + ((size_t)(kn + row) * NKV + kvh) * HD + c8);
            }
            CP_COMMIT();
            CP_WAIT(1);             // VT_t done (K_{t+1} pending)
        } else {
            CP_WAIT(0);
        }
        __syncthreads();            // VT_t + Ps visible

        // O += P * V : warp m16 x n128 x k64
#pragma unroll
        for (int kk = 0; kk < 64; kk += 16) {
            uint32_t a[4];
            ldsm4(a, smem_u32(Ps + (m0 + arow) * PSTRh + kk + acol));
#pragma unroll
            for (int np = 0; np < 8; np++) {
                uint32_t bb[4];
                ldsm4(bb, smem_u32(VTs + ((np * 2 + bnt) * 8 + brow) * VTSTRh + kk + bk8));
                mma_f16(o[np * 2 + 0], a, bb);
                mma_f16(o[np * 2 + 1], a, bb + 2);
            }
        }
        __syncthreads();            // PV done everywhere

        // issue VT_{t+1}
        if (t < tmax) {
            const int kn = k0 + 64;
            for (int f = tid; f < 128 * 8; f += 256) {
                int d = f >> 3, c8 = (f & 7) * 8;
                cp16(smem_u32(VTs + d * VTSTRh + c8),
                     g_vtT + ((size_t)(kvh * HD + d)) * SEQ + kn + c8);
            }
            CP_COMMIT();
        }
    }

    // normalize + write fp16 (A operand of O projection)
    float inv0 = 1.f / li0, inv1 = 1.f / li1;
#pragma unroll
    for (int nt = 0; nt < 16; nt++) {
        int c = nt * 8 + 2 * tg;
        size_t b0 = ((size_t)qr0 * NH + head) * HD + c;
        size_t b1 = ((size_t)qr1 * NH + head) * HD + c;
        *(__half2*)(g_ot + b0) = __floats2half2_rn(o[nt][0] * inv0, o[nt][1] * inv0);
        *(__half2*)(g_ot + b1) = __floats2half2_rn(o[nt][2] * inv1, o[nt][3] * inv1);
    }
}

// ---------------- launch -----------------------------------------------------
extern "C" void kernel_launch(void* const* d_in, const int* in_sizes, int n_in,
                              void* d_out, int out_size)
{
    const float* hidden = (const float*)d_in[0];
    const float* cosT   = (const float*)d_in[1];
    const float* sinT   = (const float*)d_in[2];
    const int*   doc    = (const int*)  d_in[3];
    const float* Wq = (const float*)d_in[5];
    const float* bq = (const float*)d_in[6];
    const float* Wk = (const float*)d_in[7];
    const float* bk = (const float*)d_in[8];
    const float* Wv = (const float*)d_in[9];
    const float* bv = (const float*)d_in[10];
    const float* Wo = (const float*)d_in[11];
    float* out = (float*)d_out;

    // 1) fused fp32 -> fp16 conversion of hidden + all weights (1 launch)
    conv_all<<<(int)(CTOT / 8 / 256), 256>>>(hidden, Wq, Wk, Wv, Wo);

    // 2) fused QKV projections (fp16 HMMA + ldmatrix; V written transposed)
    cudaFuncSetAttribute(gemm_qkv, cudaFuncAttributeMaxDynamicSharedMemorySize, GEMM_SMEM);
    gemm_qkv<<<dim3(36, SEQ / 128), 256, GEMM_SMEM>>>(bq, bk, bv);

    // 3) RoPE + fp16 for Q/K
    prep_rope<<<dim3(SEQ, 4), HD>>>(cosT, sinT);

    // 4) flash attention (fp16 HMMA + ldmatrix)
    cudaFuncSetAttribute(flash_kernel, cudaFuncAttributeMaxDynamicSharedMemorySize, FLASH_SMEM);
    flash_kernel<<<dim3(SEQ / 128, NH), 256, FLASH_SMEM>>>(doc);

    // 5) output projection
    cudaFuncSetAttribute(gemm_out, cudaFuncAttributeMaxDynamicSharedMemorySize, GEMM_SMEM);
    gemm_out<<<dim3(HID / 128, SEQ / 128), 256, GEMM_SMEM>>>(out);
}

// round 12
// speedup vs baseline: 12.0736x; 1.2646x over previous
#include <cuda_runtime.h>
#include <cuda_fp16.h>
#include <math.h>
#include <stdint.h>

#define SEQ 2048
#define HID 3584
#define NH 28
#define NKV 4
#define GRP 7
#define HD 128
#define SOFT_SCALE 0.08838834764831845f     // 1/sqrt(128)
#define SCALE_LG2  0.12751500885282288f     // SOFT_SCALE * log2(e)

// ---------------- scratch (static device globals; no runtime allocation) ----
__device__ __half g_hid_t[SEQ * HID];
__device__ __half g_wq_t[NH * HD * HID];
__device__ __half g_wk_t[NKV * HD * HID];
__device__ __half g_wv_t[NKV * HD * HID];
__device__ __half g_wo_t[HID * NH * HD];
__device__ float  g_q[SEQ * NH * HD];        // Q pre-rope fp32
__device__ float  g_k[SEQ * NKV * HD];       // K pre-rope fp32
__device__ __half g_qt[SEQ * NH * HD];       // rope(Q) fp16
__device__ __half g_kt[SEQ * NKV * HD];      // rope(K) fp16
__device__ __half g_vtT[NKV * HD * SEQ];     // V fp16 TRANSPOSED [h*d][s]
__device__ __half g_ot[SEQ * NH * HD];       // attn out fp16

// ---------------- helpers ----------------------------------------------------
__device__ __forceinline__ void mma_f16(float* c, const uint32_t* a, const uint32_t* b) {
    asm volatile(
        "mma.sync.aligned.m16n8k16.row.col.f32.f16.f16.f32 "
        "{%0,%1,%2,%3}, {%4,%5,%6,%7}, {%8,%9}, {%0,%1,%2,%3};"
        : "+f"(c[0]), "+f"(c[1]), "+f"(c[2]), "+f"(c[3])
        : "r"(a[0]), "r"(a[1]), "r"(a[2]), "r"(a[3]), "r"(b[0]), "r"(b[1]));
}
__device__ __forceinline__ void ldsm4(uint32_t* r, uint32_t addr) {
    asm volatile("ldmatrix.sync.aligned.m8n8.x4.shared.b16 {%0,%1,%2,%3}, [%4];"
        : "=r"(r[0]), "=r"(r[1]), "=r"(r[2]), "=r"(r[3]) : "r"(addr));
}
__device__ __forceinline__ uint32_t smem_u32(const void* p) {
    return (uint32_t)__cvta_generic_to_shared(p);
}
__device__ __forceinline__ void cp16(uint32_t s, const void* g) {
    asm volatile("cp.async.cg.shared.global [%0], [%1], 16;" :: "r"(s), "l"(g));
}
#define CP_COMMIT() asm volatile("cp.async.commit_group;" ::: "memory")
#define CP_WAIT(n)  asm volatile("cp.async.wait_group %0;" :: "n"(n) : "memory")

// ---------------- single fused fp32 -> fp16 converter ------------------------
#define CN0 ((long)SEQ * HID)
#define CN1 ((long)NH * HD * HID)
#define CN2 ((long)NKV * HD * HID)
#define CTOT (CN0 + CN1 + 2 * CN2 + CN1)

__global__ void conv_all(const float* __restrict__ h, const float* __restrict__ wq,
                         const float* __restrict__ wk, const float* __restrict__ wv,
                         const float* __restrict__ wo)
{
    long i = ((long)blockIdx.x * blockDim.x + threadIdx.x) * 8;
    const float* s; __half* d; long off;
    if (i < CN0)                       { s = h;  d = g_hid_t; off = i; }
    else if (i < CN0 + CN1)            { s = wq; d = g_wq_t;  off = i - CN0; }
    else if (i < CN0 + CN1 + CN2)      { s = wk; d = g_wk_t;  off = i - CN0 - CN1; }
    else if (i < CN0 + CN1 + 2 * CN2)  { s = wv; d = g_wv_t;  off = i - CN0 - CN1 - CN2; }
    else                               { s = wo; d = g_wo_t;  off = i - CN0 - CN1 - 2 * CN2; }
    float4 x = *(const float4*)(s + off);
    float4 y = *(const float4*)(s + off + 4);
    __half hh[8] = { __float2half_rn(x.x), __float2half_rn(x.y),
                     __float2half_rn(x.z), __float2half_rn(x.w),
                     __float2half_rn(y.x), __float2half_rn(y.y),
                     __float2half_rn(y.z), __float2half_rn(y.w) };
    *(uint4*)(d + off) = *(uint4*)hh;
}

// ---------------- rope + fp16 (natural layout) -------------------------------
__global__ void prep_rope(const float* __restrict__ cosT, const float* __restrict__ sinT)
{
    const int s = blockIdx.x, d = threadIdx.x;
    const float c  = cosT[s * HD + d];
    const float sn = sinT[s * HD + d];
    const float sg = (d < 64) ? -1.f : 1.f;

#pragma unroll
    for (int i = 0; i < 7; i++) {
        int h = blockIdx.y * 7 + i;
        size_t base = ((size_t)s * NH + h) * HD;
        float x  = g_q[base + d];
        float xo = g_q[base + (d ^ 64)];
        g_qt[base + d] = __float2half_rn(fmaf(sg * xo, sn, x * c));
    }
    {
        size_t base = ((size_t)s * NKV + blockIdx.y) * HD;
        float x  = g_k[base + d];
        float xo = g_k[base + (d ^ 64)];
        g_kt[base + d] = __float2half_rn(fmaf(sg * xo, sn, x * c));
    }
}

// ---------------- FP16 tensor GEMM: C = A[M,K]*B[N,K]^T + bias ---------------
#define GSTRh 72
#define GSTAGEh (128 * GSTRh)
#define GEMM_SMEM (3 * GSTAGEh * 2 * 2)   // bytes

// MODE: 0 = fp32 out + bias, 1 = V: fp16 transposed out + bias, 2 = fp32 no bias
template <int MODE>
__device__ __forceinline__ void gemm_body(
    const __half* __restrict__ A, const __half* __restrict__ B,
    const float* __restrict__ bias, void* __restrict__ C,
    int N, int K, int bx, int by, __half* As, __half* Bs)
{
    const int tid  = threadIdx.x;
    const int warp = tid >> 5, lane = tid & 31;
    const int g = lane >> 2, tg = lane & 3;
    const int wm = (warp >> 2) * 64;
    const int wn = (warp & 3) * 32;
    const int arow = lane & 15, acol = (lane >> 4) << 3;
    const int brow = lane & 7, bk8 = ((lane >> 3) & 1) << 3;
    const int bnt  = lane >> 4;

    float acc[16][4];
#pragma unroll
    for (int i = 0; i < 16; i++)
#pragma unroll
        for (int j = 0; j < 4; j++) acc[i][j] = 0.f;

    const int T = K / 64;

#define LOAD_TILE(t_)                                                            \
    do {                                                                         \
        __half* ab_ = As + ((t_) % 3) * GSTAGEh;                                 \
        __half* bb_ = Bs + ((t_) % 3) * GSTAGEh;                                 \
        _Pragma("unroll")                                                        \
        for (int i_ = 0; i_ < 4; i_++) {                                         \
            int f_ = tid + i_ * 256;                                             \
            int row_ = f_ >> 3, ch_ = (f_ & 7) * 8;                              \
            cp16(smem_u32(ab_ + row_ * GSTRh + ch_),                             \
                 A + (size_t)(by * 128 + row_) * K + (t_) * 64 + ch_);           \
            cp16(smem_u32(bb_ + row_ * GSTRh + ch_),                             \
                 B + (size_t)(bx * 128 + row_) * K + (t_) * 64 + ch_);           \
        }                                                                        \
        CP_COMMIT();                                                             \
    } while (0)

    LOAD_TILE(0);
    LOAD_TILE(1);

    for (int t = 0; t < T; t++) {
        if (t < T - 1) CP_WAIT(1); else CP_WAIT(0);
        __syncthreads();

        if (t + 2 < T) LOAD_TILE(t + 2);

        const __half* as = As + (t % 3) * GSTAGEh;
        const __half* bs = Bs + (t % 3) * GSTAGEh;
#pragma unroll
        for (int kk = 0; kk < 64; kk += 16) {
            uint32_t a[4][4], bb[2][4];
#pragma unroll
            for (int mt = 0; mt < 4; mt++)
                ldsm4(a[mt], smem_u32(as + (wm + mt * 16 + arow) * GSTRh + kk + acol));
#pragma unroll
            for (int np = 0; np < 2; np++)
                ldsm4(bb[np], smem_u32(bs + (wn + (np * 2 + bnt) * 8 + brow) * GSTRh + kk + bk8));
#pragma unroll
            for (int mt = 0; mt < 4; mt++)
#pragma unroll
                for (int nt = 0; nt < 4; nt++)
                    mma_f16(acc[mt * 4 + nt], a[mt], &bb[nt >> 1][(nt & 1) * 2]);
        }
    }
    __syncthreads();

#pragma unroll
    for (int mt = 0; mt < 4; mt++) {
#pragma unroll
        for (int nt = 0; nt < 4; nt++) {
            int r0 = by * 128 + wm + mt * 16 + g;
            int c0 = bx * 128 + wn + nt * 8 + 2 * tg;
            float b0 = (MODE != 2) ? bias[c0] : 0.f;
            float b1 = (MODE != 2) ? bias[c0 + 1] : 0.f;
            float* ca = acc[mt * 4 + nt];
            if (MODE == 1) {
                __half* Co = (__half*)C;   // g_vtT: [c][s]
                Co[(size_t)c0 * SEQ + r0]           = __float2half_rn(ca[0] + b0);
                Co[(size_t)(c0 + 1) * SEQ + r0]     = __float2half_rn(ca[1] + b1);
                Co[(size_t)c0 * SEQ + r0 + 8]       = __float2half_rn(ca[2] + b0);
                Co[(size_t)(c0 + 1) * SEQ + r0 + 8] = __float2half_rn(ca[3] + b1);
            } else {
                float* Co = (float*)C;
                *(float2*)(&Co[(size_t)r0 * N + c0])       = make_float2(ca[0] + b0, ca[1] + b1);
                *(float2*)(&Co[(size_t)(r0 + 8) * N + c0]) = make_float2(ca[2] + b0, ca[3] + b1);
            }
        }
    }
#undef LOAD_TILE
}

__global__ __launch_bounds__(256) void gemm_qkv(
    const float* __restrict__ bq, const float* __restrict__ bk,
    const float* __restrict__ bv)
{
    extern __shared__ __align__(16) __half gsm[];
    __half* As = gsm;
    __half* Bs = gsm + 3 * GSTAGEh;
    const int bx = blockIdx.x, by = blockIdx.y;
    if (bx < 28)
        gemm_body<0>(g_hid_t, g_wq_t, bq, g_q, NH * HD, HID, bx, by, As, Bs);
    else if (bx < 32)
        gemm_body<0>(g_hid_t, g_wk_t, bk, g_k, NKV * HD, HID, bx - 28, by, As, Bs);
    else
        gemm_body<1>(g_hid_t, g_wv_t, bv, g_vtT, NKV * HD, HID, bx - 32, by, As, Bs);
}

__global__ __launch_bounds__(256) void gemm_out(float* __restrict__ C)
{
    extern __shared__ __align__(16) __half gsm[];
    gemm_body<2>(g_ot, g_wo_t, nullptr, C, HID, HID, blockIdx.x, blockIdx.y,
                 gsm, gsm + 3 * GSTAGEh);
}

// ---------------- Flash attention (doc-aware tile skipping) ------------------
// BQ=128, BKV=64. 8 warps; warp owns 16 query rows. K double-buffered,
// V^T single-buffered. Softmax in log2 domain (exp2f).
#define QSTRh 136
#define KSTRh 136
#define VTSTRh 72
#define PSTRh 72
#define KVTILEh (64 * KSTRh)
#define FLASH_SMEM ((128*QSTRh + 2*KVTILEh + 128*VTSTRh + 128*PSTRh) * 2 + 64 * 4)

__global__ __launch_bounds__(256) void flash_kernel(const int* __restrict__ doc)
{
    extern __shared__ __align__(16) __half fsm[];
    __half* Qs  = fsm;                        // [128][QSTRh]
    __half* Ks  = Qs + 128 * QSTRh;           // 2 x [64][KSTRh]
    __half* VTs = Ks + 2 * KVTILEh;           // [128 d][VTSTRh]
    __half* Ps  = VTs + 128 * VTSTRh;         // [128][PSTRh]
    int* kdoc = (int*)(Ps + 128 * PSTRh);

    const int qb = gridDim.x - 1 - blockIdx.x;
    const int head = blockIdx.y;
    const int kvh = head / GRP;
    const int q0 = qb * 128;
    const int tid = threadIdx.x;
    const int warp = tid >> 5, lane = tid & 31;
    const int g = lane >> 2, tg = lane & 3;
    const int m0 = warp * 16;
    const int arow = lane & 15, acol = (lane >> 4) << 3;
    const int brow = lane & 7, bk8 = ((lane >> 3) & 1) << 3;
    const int bnt  = lane >> 4;

    // doc-aware start tile: first KV tile containing doc[q0]'s document start.
    const int dq_lo = __ldg(doc + q0), dq_hi = __ldg(doc + q0 + 127);
    int lo = 0, hi = q0;
    while (lo < hi) {                        // first idx with doc[idx] >= dq_lo
        int mid = (lo + hi) >> 1;
        if (__ldg(doc + mid) < dq_lo) lo = mid + 1; else hi = mid;
    }
    const int t0 = lo >> 6;
    const int tmax = 2 * qb + 1;
    const bool q_split = (dq_lo != dq_hi);

    // prologue: Q, K[t0], VT[t0]
    for (int f = tid; f < 128 * 16; f += 256) {
        int row = f >> 4, c8 = (f & 15) * 8;
        cp16(smem_u32(Qs + row * QSTRh + c8),
             g_qt + ((size_t)(q0 + row) * NH + head) * HD + c8);
    }
    CP_COMMIT();
    for (int f = tid; f < 64 * 16; f += 256) {
        int row = f >> 4, c8 = (f & 15) * 8;
        cp16(smem_u32(Ks + row * KSTRh + c8),
             g_kt + ((size_t)(t0 * 64 + row) * NKV + kvh) * HD + c8);
    }
    CP_COMMIT();
    for (int f = tid; f < 128 * 8; f += 256) {
        int d = f >> 3, c8 = (f & 7) * 8;
        cp16(smem_u32(VTs + d * VTSTRh + c8),
             g_vtT + ((size_t)(kvh * HD + d)) * SEQ + t0 * 64 + c8);
    }
    CP_COMMIT();

    const int qr0 = q0 + m0 + g, qr1 = qr0 + 8;
    const int qd0 = __ldg(doc + qr0), qd1 = __ldg(doc + qr1);
    float mi0 = -1e30f, mi1 = -1e30f, li0 = 0.f, li1 = 0.f;
    float o[16][4];
#pragma unroll
    for (int i = 0; i < 16; i++)
#pragma unroll
        for (int j = 0; j < 4; j++) o[i][j] = 0.f;

    for (int t = t0; t <= tmax; t++) {
        const int k0 = t * 64;
        const int dk_lo = __ldg(doc + k0), dk_hi = __ldg(doc + k0 + 63);
        const bool need_mask = (t >= 2 * qb) | (dk_lo != dk_hi) |
                               (dk_lo != dq_lo) | q_split;
        if (need_mask && tid < 64) kdoc[tid] = doc[k0 + tid];
        CP_WAIT(1);                 // Q + K_t done (VT_t may pend)
        __syncthreads();

        const __half* ks = Ks + (t & 1) * KVTILEh;

        // scores: warp m16 x n64 x k128
        float s[8][4];
#pragma unroll
        for (int i = 0; i < 8; i++)
#pragma unroll
            for (int j = 0; j < 4; j++) s[i][j] = 0.f;

#pragma unroll
        for (int kk = 0; kk < 128; kk += 16) {
            uint32_t a[4];
            ldsm4(a, smem_u32(Qs + (m0 + arow) * QSTRh + kk + acol));
#pragma unroll
            for (int np = 0; np < 4; np++) {
                uint32_t bb[4];
                ldsm4(bb, smem_u32(ks + ((np * 2 + bnt) * 8 + brow) * KSTRh + kk + bk8));
                mma_f16(s[np * 2 + 0], a, bb);
                mma_f16(s[np * 2 + 1], a, bb + 2);
            }
        }

        // scale into log2 domain (+ mask if needed) + row max
        float mx0 = -1e30f, mx1 = -1e30f;
        if (need_mask) {
#pragma unroll
            for (int nt = 0; nt < 8; nt++) {
                int c0 = k0 + nt * 8 + 2 * tg;
                int d0 = kdoc[nt * 8 + 2 * tg];
                int d1 = kdoc[nt * 8 + 2 * tg + 1];
                s[nt][0] = (qr0 >= c0     && qd0 == d0) ? s[nt][0] * SCALE_LG2 : -1e30f;
                s[nt][1] = (qr0 >= c0 + 1 && qd0 == d1) ? s[nt][1] * SCALE_LG2 : -1e30f;
                s[nt][2] = (qr1 >= c0     && qd1 == d0) ? s[nt][2] * SCALE_LG2 : -1e30f;
                s[nt][3] = (qr1 >= c0 + 1 && qd1 == d1) ? s[nt][3] * SCALE_LG2 : -1e30f;
                mx0 = fmaxf(mx0, fmaxf(s[nt][0], s[nt][1]));
                mx1 = fmaxf(mx1, fmaxf(s[nt][2], s[nt][3]));
            }
        } else {
#pragma unroll
            for (int nt = 0; nt < 8; nt++) {
                s[nt][0] *= SCALE_LG2; s[nt][1] *= SCALE_LG2;
                s[nt][2] *= SCALE_LG2; s[nt][3] *= SCALE_LG2;
                mx0 = fmaxf(mx0, fmaxf(s[nt][0], s[nt][1]));
                mx1 = fmaxf(mx1, fmaxf(s[nt][2], s[nt][3]));
            }
        }
        mx0 = fmaxf(mx0, __shfl_xor_sync(0xffffffffu, mx0, 1));
        mx0 = fmaxf(mx0, __shfl_xor_sync(0xffffffffu, mx0, 2));
        mx1 = fmaxf(mx1, __shfl_xor_sync(0xffffffffu, mx1, 1));
        mx1 = fmaxf(mx1, __shfl_xor_sync(0xffffffffu, mx1, 2));

        float nm0 = fmaxf(mi0, mx0), nm1 = fmaxf(mi1, mx1);
        float cr0 = exp2f(mi0 - nm0), cr1 = exp2f(mi1 - nm1);
        mi0 = nm0; mi1 = nm1;
#pragma unroll
        for (int nt = 0; nt < 16; nt++) {
            o[nt][0] *= cr0; o[nt][1] *= cr0;
            o[nt][2] *= cr1; o[nt][3] *= cr1;
        }

        float rs0 = 0.f, rs1 = 0.f;
#pragma unroll
        for (int nt = 0; nt < 8; nt++) {
            float pe0 = (s[nt][0] > -1e29f) ? exp2f(s[nt][0] - nm0) : 0.f;
            float pe1 = (s[nt][1] > -1e29f) ? exp2f(s[nt][1] - nm0) : 0.f;
            float pe2 = (s[nt][2] > -1e29f) ? exp2f(s[nt][2] - nm1) : 0.f;
            float pe3 = (s[nt][3] > -1e29f) ? exp2f(s[nt][3] - nm1) : 0.f;
            rs0 += pe0 + pe1; rs1 += pe2 + pe3;
            int c = nt * 8 + 2 * tg;
            *(__half2*)(Ps + (m0 + g) * PSTRh + c)     = __floats2half2_rn(pe0, pe1);
            *(__half2*)(Ps + (m0 + 8 + g) * PSTRh + c) = __floats2half2_rn(pe2, pe3);
        }
        rs0 += __shfl_xor_sync(0xffffffffu, rs0, 1);
        rs0 += __shfl_xor_sync(0xffffffffu, rs0, 2);
        rs1 += __shfl_xor_sync(0xffffffffu, rs1, 1);
        rs1 += __shfl_xor_sync(0xffffffffu, rs1, 2);
        li0 = li0 * cr0 + rs0;
        li1 = li1 * cr1 + rs1;

        // prefetch K_{t+1}; then wait own VT_t
        if (t < tmax) {
            const int kn = k0 + 64;
            __half* kd = Ks + ((t + 1) & 1) * KVTILEh;
            for (int f = tid; f < 64 * 16; f += 256) {
                int row = f >> 4, c8 = (f & 15) * 8;
                cp16(smem_u32(kd + row * KSTRh + c8),
                     g_kt + ((size_t)(kn + row) * NKV + kvh) * HD + c8);
            }
            CP_COMMIT();
            CP_WAIT(1);             // VT_t done (K_{t+1} pending)
        } else {
            CP_WAIT(0);
        }
        __syncthreads();            // VT_t + Ps visible

        // O += P * V : warp m16 x n128 x k64
#pragma unroll
        for (int kk = 0; kk < 64; kk += 16) {
            uint32_t a[4];
            ldsm4(a, smem_u32(Ps + (m0 + arow) * PSTRh + kk + acol));
#pragma unroll
            for (int np = 0; np < 8; np++) {
                uint32_t bb[4];
                ldsm4(bb, smem_u32(VTs + ((np * 2 + bnt) * 8 + brow) * VTSTRh + kk + bk8));
                mma_f16(o[np * 2 + 0], a, bb);
                mma_f16(o[np * 2 + 1], a, bb + 2);
            }
        }
        __syncthreads();            // PV done everywhere

        // issue VT_{t+1}
        if (t < tmax) {
            const int kn = k0 + 64;
            for (int f = tid; f < 128 * 8; f += 256) {
                int d = f >> 3, c8 = (f & 7) * 8;
                cp16(smem_u32(VTs + d * VTSTRh + c8),
                     g_vtT + ((size_t)(kvh * HD + d)) * SEQ + kn + c8);
            }
            CP_COMMIT();
        }
    }

    // normalize + write fp16 (A operand of O projection)
    float inv0 = 1.f / li0, inv1 = 1.f / li1;
#pragma unroll
    for (int nt = 0; nt < 16; nt++) {
        int c = nt * 8 + 2 * tg;
        size_t b0 = ((size_t)qr0 * NH + head) * HD + c;
        size_t b1 = ((size_t)qr1 * NH + head) * HD + c;
        *(__half2*)(g_ot + b0) = __floats2half2_rn(o[nt][0] * inv0, o[nt][1] * inv0);
        *(__half2*)(g_ot + b1) = __floats2half2_rn(o[nt][2] * inv1, o[nt][3] * inv1);
    }
}

// ---------------- launch -----------------------------------------------------
extern "C" void kernel_launch(void* const* d_in, const int* in_sizes, int n_in,
                              void* d_out, int out_size)
{
    const float* hidden = (const float*)d_in[0];
    const float* cosT   = (const float*)d_in[1];
    const float* sinT   = (const float*)d_in[2];
    const int*   doc    = (const int*)  d_in[3];
    const float* Wq = (const float*)d_in[5];
    const float* bq = (const float*)d_in[6];
    const float* Wk = (const float*)d_in[7];
    const float* bk = (const float*)d_in[8];
    const float* Wv = (const float*)d_in[9];
    const float* bv = (const float*)d_in[10];
    const float* Wo = (const float*)d_in[11];
    float* out = (float*)d_out;

    // 1) fused fp32 -> fp16 conversion (1 launch)
    conv_all<<<(int)(CTOT / 8 / 256), 256>>>(hidden, Wq, Wk, Wv, Wo);

    // 2) fused QKV projections
    cudaFuncSetAttribute(gemm_qkv, cudaFuncAttributeMaxDynamicSharedMemorySize, GEMM_SMEM);
    gemm_qkv<<<dim3(36, SEQ / 128), 256, GEMM_SMEM>>>(bq, bk, bv);

    // 3) RoPE + fp16 for Q/K
    prep_rope<<<dim3(SEQ, 4), HD>>>(cosT, sinT);

    // 4) flash attention (doc-aware tile skipping)
    cudaFuncSetAttribute(flash_kernel, cudaFuncAttributeMaxDynamicSharedMemorySize, FLASH_SMEM);
    flash_kernel<<<dim3(SEQ / 128, NH), 256, FLASH_SMEM>>>(doc);

    // 5) output projection
    cudaFuncSetAttribute(gemm_out, cudaFuncAttributeMaxDynamicSharedMemorySize, GEMM_SMEM);
    gemm_out<<<dim3(HID / 128, SEQ / 128), 256, GEMM_SMEM>>>(out);
}